// round 13
// baseline (speedup 1.0000x reference)
#include <cuda_runtime.h>
#include <cuda_bf16.h>
#include <math.h>
#include <stdint.h>

// ---------------- problem constants ----------------
#define BATCH 2
#define CDIM 96
#define HEADS 2
#define CH 48
#define QKV 288
#define HID 255
#define HIDP 256
#define H2 510
#define H2P 512
#define NPIX 131072

typedef __nv_bfloat16 bf16;

// ---------------- device scratch ----------------
__device__ __align__(256) bf16 g_t0[(size_t)NPIX * QKV];
__device__ __align__(256) bf16 g_t1[(size_t)NPIX * QKV];
__device__ __align__(256) bf16 g_t2[(size_t)NPIX * H2P];
__device__ __align__(256) bf16 g_gt[(size_t)NPIX * HIDP];
__device__ __align__(256) bf16 g_ybf[(size_t)NPIX * CDIM];
__device__ __align__(256) float g_x2[(size_t)NPIX * CDIM];
__device__ float g_nrm[2 * BATCH * CDIM];
__device__ float g_att[BATCH * HEADS * CH * CH];
__device__ __align__(256) bf16 g_wq[CDIM * QKV];
__device__ __align__(256) bf16 g_wa[CDIM * CDIM];
__device__ __align__(256) bf16 g_wip[CDIM * H2P];
__device__ __align__(256) bf16 g_wo2[HIDP * CDIM];
__device__ __align__(256) float g_kwp[9 * H2P];

// ---------------- helpers ----------------
__device__ __forceinline__ float gelu_exact(float v) {
    return 0.5f * v * (1.0f + erff(v * 0.70710678118654752f));
}
__device__ __forceinline__ void ldsm_x4(uint32_t* r, uint32_t addr) {
    asm volatile("ldmatrix.sync.aligned.m8n8.x4.shared.b16 {%0,%1,%2,%3}, [%4];"
        : "=r"(r[0]), "=r"(r[1]), "=r"(r[2]), "=r"(r[3]) : "r"(addr));
}
__device__ __forceinline__ void ldsm_x4_t(uint32_t* r, uint32_t addr) {
    asm volatile("ldmatrix.sync.aligned.m8n8.x4.trans.shared.b16 {%0,%1,%2,%3}, [%4];"
        : "=r"(r[0]), "=r"(r[1]), "=r"(r[2]), "=r"(r[3]) : "r"(addr));
}
__device__ __forceinline__ void mma_bf16(float* c, const uint32_t* a, const uint32_t* b) {
    asm volatile("mma.sync.aligned.m16n8k16.row.col.f32.bf16.bf16.f32 "
        "{%0,%1,%2,%3}, {%4,%5,%6,%7}, {%8,%9}, {%0,%1,%2,%3};\n"
        : "+f"(c[0]), "+f"(c[1]), "+f"(c[2]), "+f"(c[3])
        : "r"(a[0]), "r"(a[1]), "r"(a[2]), "r"(a[3]), "r"(b[0]), "r"(b[1]));
}
__device__ __forceinline__ uint32_t pack_bf2(float a, float b) {
    __nv_bfloat162 h = __floats2bfloat162_rn(a, b);
    return *(uint32_t*)&h;
}
__device__ __forceinline__ void cp16(uint32_t dst, const void* src) {
    asm volatile("cp.async.ca.shared.global [%0], [%1], 16;" :: "r"(dst), "l"(src));
}
#define CP_COMMIT() asm volatile("cp.async.commit_group;")
__device__ __forceinline__ void cp_wait0() { asm volatile("cp.async.wait_group 0;"); }
__device__ __forceinline__ void cp_wait1() { asm volatile("cp.async.wait_group 1;"); }

// ---------------- weight convert / remap + accumulator init ----------------
__global__ void cvt_all_kernel(const float* wq, const float* wa, const float* wi, const float* wo,
                               const float* fdw,
                               bf16* dq, bf16* da, bf16* dip, bf16* dxo2,
                               float* kwp, float* nrm, float* attn) {
    int i = blockIdx.x * blockDim.x + threadIdx.x;
    const int s0 = CDIM * QKV, s1 = s0 + CDIM * CDIM;
    if (i < s0) dq[i] = __float2bfloat16_rn(wq[i]);
    else if (i < s1) da[i - s0] = __float2bfloat16_rn(wa[i - s0]);
    if (i < CDIM * H2P) {
        int r = i >> 9, c = i & 511;
        float v = 0.f;
        if (c < 255) v = wi[r * H2 + c];
        else if (c >= 256 && c <= 510) v = wi[r * H2 + c - 1];
        dip[i] = __float2bfloat16_rn(v);
    }
    if (i < HIDP * CDIM) {
        int r = i / CDIM;
        dxo2[i] = (r < HID) ? __float2bfloat16_rn(wo[i]) : __float2bfloat16_rn(0.f);
    }
    if (i < 9 * H2P) {
        int d = i >> 9, c = i & 511;
        float v = 0.f;
        if (c < 255) v = fdw[d * H2 + c];
        else if (c >= 256 && c <= 510) v = fdw[d * H2 + c - 1];
        kwp[i] = v;
    }
    if (i < 2 * BATCH * CDIM) nrm[i] = 0.f;
    if (i < BATCH * HEADS * CH * CH) attn[i] = 0.f;
}

// ---------------- generic B-resident GEMM, K=96, multi-pass N, optional fused LN on A ----------------
template<int NPASS, int NT, bool FUSE_LN>
__global__ void __launch_bounds__(256)
gemm_bres(const bf16* __restrict__ Abf, const float* __restrict__ Xf,
          const float* __restrict__ gamma, const float* __restrict__ beta,
          const bf16* __restrict__ Bw, bf16* __restrict__ Cout, int Nglob) {
    constexpr int PASSW = NT * 16;
    constexpr int BCOLS = NPASS * PASSW;
    constexpr int PA = 104;
    constexpr int PB = BCOLS + 8;
    extern __shared__ char smraw[];
    bf16* As = (bf16*)smraw;
    bf16* Bs = (bf16*)smraw + 128 * PA;
    uint32_t as_base = (uint32_t)__cvta_generic_to_shared(smraw);
    uint32_t bs_base = as_base + 128 * PA * 2;

    int tid = threadIdx.x, lane = tid & 31, warp = tid >> 5;
    int m0 = blockIdx.y * 128;
    int ncol0 = blockIdx.x * BCOLS;
    int g = lane >> 2, tg = lane & 3;
    int warpM = warp & 3, warpN = warp >> 2;
    int mbase = warpM * 32, nbase = warpN * (NT * 8);

    constexpr int BU = 96 * (BCOLS / 2);
    #pragma unroll
    for (int l = 0; l < BU / 256; l++) {
        int idx = tid + l * 256;
        int row = idx / (BCOLS / 2), nu = idx % (BCOLS / 2);
        *(uint32_t*)&Bs[row * PB + nu * 2] =
            *(const uint32_t*)(Bw + (size_t)row * Nglob + ncol0 + nu * 2);
    }

    if (FUSE_LN) {
        float ga0 = gamma[lane], ga1 = gamma[lane + 32], ga2 = gamma[lane + 64];
        float be0 = beta[lane],  be1 = beta[lane + 32],  be2 = beta[lane + 64];
        #pragma unroll
        for (int i = 0; i < 16; i++) {
            int row = warp * 16 + i;
            const float* xp = Xf + (size_t)(m0 + row) * CDIM;
            float v0 = xp[lane], v1 = xp[lane + 32], v2 = xp[lane + 64];
            float s  = v0 + v1 + v2;
            float ss = v0 * v0 + v1 * v1 + v2 * v2;
            #pragma unroll
            for (int o = 16; o > 0; o >>= 1) {
                s  += __shfl_xor_sync(0xffffffffu, s,  o);
                ss += __shfl_xor_sync(0xffffffffu, ss, o);
            }
            float mu = s * (1.f / 96.f);
            float var = ss * (1.f / 96.f) - mu * mu;
            float rstd = rsqrtf(var + 1e-5f);
            As[row * PA + lane]      = __float2bfloat16_rn((v0 - mu) * rstd * ga0 + be0);
            As[row * PA + lane + 32] = __float2bfloat16_rn((v1 - mu) * rstd * ga1 + be1);
            As[row * PA + lane + 64] = __float2bfloat16_rn((v2 - mu) * rstd * ga2 + be2);
        }
    } else {
        #pragma unroll
        for (int l = 0; l < 6; l++) {
            int idx = tid + l * 256;
            int row = idx / 12, c8 = idx % 12;
            *(uint4*)&As[row * PA + c8 * 8] =
                *(const uint4*)(Abf + (size_t)(m0 + row) * CDIM + c8 * 8);
        }
    }
    __syncthreads();

    uint32_t a_addr[2], b_addr0[NT / 2];
    {
        int arow = lane & 15, acol = (lane >> 4) << 3;
        a_addr[0] = as_base + (uint32_t)(((mbase + arow) * PA + acol) * 2);
        a_addr[1] = as_base + (uint32_t)(((mbase + 16 + arow) * PA + acol) * 2);
        int krow = ((lane >> 3) & 1) * 8 + (lane & 7);
        int coff = (lane >> 4) << 3;
        #pragma unroll
        for (int nh = 0; nh < NT / 2; nh++)
            b_addr0[nh] = bs_base + (uint32_t)((krow * PB + nbase + nh * 16 + coff) * 2);
    }

    #pragma unroll
    for (int pass = 0; pass < NPASS; pass++) {
        float acc[2][NT][4];
        #pragma unroll
        for (int mt = 0; mt < 2; mt++)
            #pragma unroll
            for (int nt = 0; nt < NT; nt++)
                #pragma unroll
                for (int i = 0; i < 4; i++) acc[mt][nt][i] = 0.f;

        uint32_t poff = (uint32_t)(pass * PASSW * 2);
        #pragma unroll
        for (int ks = 0; ks < 6; ks++) {
            uint32_t af[2][4];
            ldsm_x4(af[0], a_addr[0] + ks * 32);
            ldsm_x4(af[1], a_addr[1] + ks * 32);
            #pragma unroll
            for (int nh = 0; nh < NT / 2; nh++) {
                uint32_t bq[4];
                ldsm_x4_t(bq, b_addr0[nh] + poff + ks * 16 * (PB * 2));
                #pragma unroll
                for (int mt = 0; mt < 2; mt++) {
                    mma_bf16(acc[mt][nh * 2 + 0], af[mt], &bq[0]);
                    mma_bf16(acc[mt][nh * 2 + 1], af[mt], &bq[2]);
                }
            }
        }
        #pragma unroll
        for (int mt = 0; mt < 2; mt++) {
            #pragma unroll
            for (int nt = 0; nt < NT; nt++) {
                int col = ncol0 + pass * PASSW + nbase + nt * 8 + tg * 2;
                #pragma unroll
                for (int h = 0; h < 2; h++) {
                    int row = m0 + mbase + mt * 16 + g + h * 8;
                    size_t o = (size_t)row * Nglob + col;
                    *(uint32_t*)(Cout + o) = pack_bf2(acc[mt][nt][h * 2 + 0],
                                                      acc[mt][nt][h * 2 + 1]);
                }
            }
        }
    }
}

// ---------------- dedicated ffn_out GEMM: K=256 (padded), B resident, A pipelined ----------------
__global__ void __launch_bounds__(256)
gemm_ffnout(const bf16* __restrict__ A, const bf16* __restrict__ Bw,
            const float* __restrict__ R, float* __restrict__ C) {
    constexpr int PA = 72, PB = 104;
    constexpr int ABUF = 128 * PA * 2;
    extern __shared__ char smraw[];
    uint32_t as_base = (uint32_t)__cvta_generic_to_shared(smraw);
    uint32_t bs_base = as_base + 2 * ABUF;
    bf16* Bsm = (bf16*)(smraw + 2 * ABUF);

    int tid = threadIdx.x, lane = tid & 31, warp = tid >> 5;
    int m0 = blockIdx.x * 128;
    int g = lane >> 2, tg = lane & 3;
    int warpM = warp & 3, warpN = warp >> 2;
    int mbase = warpM * 32, nbase = warpN * 48;

    #pragma unroll
    for (int l = 0; l < 48; l++) {
        int idx = tid + l * 256;
        int row = idx / 48, nu = idx % 48;
        *(uint32_t*)&Bsm[row * PB + nu * 2] = *(const uint32_t*)(Bw + (size_t)row * CDIM + nu * 2);
    }

    uint32_t a_addr[2], b_addr[3];
    {
        int arow = lane & 15, acol = (lane >> 4) << 3;
        a_addr[0] = as_base + (uint32_t)(((mbase + arow) * PA + acol) * 2);
        a_addr[1] = as_base + (uint32_t)(((mbase + 16 + arow) * PA + acol) * 2);
        int krow = ((lane >> 3) & 1) * 8 + (lane & 7);
        int coff = (lane >> 4) << 3;
        #pragma unroll
        for (int nh = 0; nh < 3; nh++)
            b_addr[nh] = bs_base + (uint32_t)((krow * PB + nbase + nh * 16 + coff) * 2);
    }

    #pragma unroll
    for (int l = 0; l < 4; l++) {
        int idx = tid + l * 256;
        int row = idx >> 3, c8 = idx & 7;
        cp16(as_base + (uint32_t)((row * PA + c8 * 8) * 2),
             A + (size_t)(m0 + row) * HIDP + c8 * 8);
    }
    CP_COMMIT();

    float acc[2][6][4];
    #pragma unroll
    for (int a = 0; a < 2; a++)
        #pragma unroll
        for (int b = 0; b < 6; b++)
            #pragma unroll
            for (int c = 0; c < 4; c++) acc[a][b][c] = 0.f;

    int bufc = 0;
    #pragma unroll
    for (int kit = 0; kit < 4; kit++) {
        if (kit < 3) {
            int k0n = (kit + 1) * 64;
            uint32_t dstb = as_base + (uint32_t)((bufc ^ 1) * ABUF);
            #pragma unroll
            for (int l = 0; l < 4; l++) {
                int idx = tid + l * 256;
                int row = idx >> 3, c8 = idx & 7;
                cp16(dstb + (uint32_t)((row * PA + c8 * 8) * 2),
                     A + (size_t)(m0 + row) * HIDP + k0n + c8 * 8);
            }
            CP_COMMIT();
            cp_wait1();
        } else {
            cp_wait0();
        }
        __syncthreads();
        uint32_t abuf = (uint32_t)(bufc * ABUF);
        #pragma unroll
        for (int ks = 0; ks < 4; ks++) {
            uint32_t af[2][4];
            ldsm_x4(af[0], a_addr[0] + abuf + ks * 32);
            ldsm_x4(af[1], a_addr[1] + abuf + ks * 32);
            int kglob = kit * 64 + ks * 16;
            #pragma unroll
            for (int nh = 0; nh < 3; nh++) {
                uint32_t bq[4];
                ldsm_x4_t(bq, b_addr[nh] + kglob * (PB * 2));
                mma_bf16(acc[0][nh * 2 + 0], af[0], &bq[0]);
                mma_bf16(acc[0][nh * 2 + 1], af[0], &bq[2]);
                mma_bf16(acc[1][nh * 2 + 0], af[1], &bq[0]);
                mma_bf16(acc[1][nh * 2 + 1], af[1], &bq[2]);
            }
        }
        __syncthreads();
        bufc ^= 1;
    }

    #pragma unroll
    for (int mt = 0; mt < 2; mt++) {
        #pragma unroll
        for (int nt = 0; nt < 6; nt++) {
            int col = nbase + nt * 8 + tg * 2;
            #pragma unroll
            for (int h = 0; h < 2; h++) {
                int row = m0 + mbase + mt * 16 + g + h * 8;
                size_t o = (size_t)row * CDIM + col;
                float2 r2 = *(const float2*)(R + o);
                *(float2*)(C + o) = make_float2(acc[mt][nt][h * 2 + 0] + r2.x,
                                                acc[mt][nt][h * 2 + 1] + r2.y);
            }
        }
    }
}

// ---------------- attn_out GEMM (N=96, K=96) with fused residual + LayerNorm2 ----------------
__global__ void __launch_bounds__(256)
gemm_attnout_ln(const bf16* __restrict__ A, const bf16* __restrict__ Bw,
                const float* __restrict__ R, float* __restrict__ x2out,
                bf16* __restrict__ yout,
                const float* __restrict__ gamma, const float* __restrict__ beta) {
    constexpr int PA = 104, PB = 104;
    __shared__ __align__(16) char buf[49152];
    bf16* As = (bf16*)buf;
    bf16* Bs = (bf16*)buf + 128 * PA;

    int tid = threadIdx.x, lane = tid & 31, warp = tid >> 5;
    int m0 = blockIdx.x * 128;
    int g = lane >> 2, tg = lane & 3;
    int warpM = warp & 3, warpN = warp >> 2;
    int mbase = warpM * 32, nbase = warpN * 48;

    #pragma unroll
    for (int l = 0; l < 6; l++) {
        int idx = tid + l * 256;
        int row = idx / 12, c8 = idx % 12;
        *(uint4*)&As[row * PA + c8 * 8] = *(const uint4*)(A + (size_t)(m0 + row) * 96 + c8 * 8);
    }
    #pragma unroll
    for (int l = 0; l < 18; l++) {
        int idx = tid + l * 256;
        int row = idx / 48, nu = idx % 48;
        *(uint32_t*)&Bs[row * PB + nu * 2] = *(const uint32_t*)(Bw + (size_t)row * 96 + nu * 2);
    }
    __syncthreads();

    uint32_t a_addr[2], b_addr[3];
    {
        int arow = lane & 15, acol = (lane >> 4) << 3;
        #pragma unroll
        for (int mt = 0; mt < 2; mt++)
            a_addr[mt] = (uint32_t)__cvta_generic_to_shared(&As[(mbase + mt * 16 + arow) * PA + acol]);
        int krow = ((lane >> 3) & 1) * 8 + (lane & 7);
        int coff = (lane >> 4) << 3;
        #pragma unroll
        for (int nh = 0; nh < 3; nh++)
            b_addr[nh] = (uint32_t)__cvta_generic_to_shared(&Bs[krow * PB + nbase + nh * 16 + coff]);
    }

    float acc[2][6][4];
    #pragma unroll
    for (int mt = 0; mt < 2; mt++)
        #pragma unroll
        for (int nt = 0; nt < 6; nt++)
            #pragma unroll
            for (int i = 0; i < 4; i++) acc[mt][nt][i] = 0.f;

    #pragma unroll
    for (int ks = 0; ks < 6; ks++) {
        uint32_t af[2][4];
        ldsm_x4(af[0], a_addr[0] + ks * 32);
        ldsm_x4(af[1], a_addr[1] + ks * 32);
        #pragma unroll
        for (int nh = 0; nh < 3; nh++) {
            uint32_t bq[4];
            ldsm_x4_t(bq, b_addr[nh] + ks * 16 * (PB * 2));
            #pragma unroll
            for (int mt = 0; mt < 2; mt++) {
                mma_bf16(acc[mt][nh * 2 + 0], af[mt], &bq[0]);
                mma_bf16(acc[mt][nh * 2 + 1], af[mt], &bq[2]);
            }
        }
    }
    __syncthreads();

    float* sx = (float*)buf;
    #pragma unroll
    for (int mt = 0; mt < 2; mt++) {
        #pragma unroll
        for (int nt = 0; nt < 6; nt++) {
            int col = nbase + nt * 8 + tg * 2;
            #pragma unroll
            for (int h = 0; h < 2; h++) {
                int rl = mbase + mt * 16 + g + h * 8;
                size_t o = (size_t)(m0 + rl) * 96 + col;
                float2 r2 = *(const float2*)(R + o);
                float v0 = acc[mt][nt][h * 2 + 0] + r2.x;
                float v1 = acc[mt][nt][h * 2 + 1] + r2.y;
                *(float2*)(x2out + o) = make_float2(v0, v1);
                int t = (rl & 3) << 3;
                *(float2*)(sx + rl * 96 + (col ^ t)) = make_float2(v0, v1);
            }
        }
    }
    __syncthreads();

    float ga0 = gamma[lane], ga1 = gamma[lane + 32], ga2 = gamma[lane + 64];
    float be0 = beta[lane],  be1 = beta[lane + 32],  be2 = beta[lane + 64];
    #pragma unroll
    for (int i = 0; i < 16; i++) {
        int wr = warp * 16 + i;
        int t = (wr & 3) << 3;
        int c0 = lane ^ t;
        float v0 = sx[wr * 96 + c0];
        float v1 = sx[wr * 96 + c0 + 32];
        float v2 = sx[wr * 96 + c0 + 64];
        float s  = v0 + v1 + v2;
        float ss = v0 * v0 + v1 * v1 + v2 * v2;
        #pragma unroll
        for (int o = 16; o > 0; o >>= 1) {
            s  += __shfl_xor_sync(0xffffffffu, s,  o);
            ss += __shfl_xor_sync(0xffffffffu, ss, o);
        }
        float mu = s * (1.f / 96.f);
        float var = ss * (1.f / 96.f) - mu * mu;
        float rstd = rsqrtf(var + 1e-5f);
        bf16* yp = yout + (size_t)(m0 + wr) * 96;
        yp[lane]      = __float2bfloat16_rn((v0 - mu) * rstd * ga0 + be0);
        yp[lane + 32] = __float2bfloat16_rn((v1 - mu) * rstd * ga1 + be1);
        yp[lane + 64] = __float2bfloat16_rn((v2 - mu) * rstd * ga2 + be2);
    }
}

// ---------------- depthwise 3x3, C=288 bf16, 4-ch chunks, 4-wide x strip ----------------
__global__ void dwconv288_kernel(const bf16* __restrict__ in, const float* __restrict__ kern,
                                 bf16* __restrict__ out) {
    const int C4 = QKV / 4;
    int idx = blockIdx.x * blockDim.x + threadIdx.x;
    if (idx >= (NPIX / 4) * C4) return;
    int c4 = idx % C4;
    int strip = idx / C4;
    int xs = (strip & 63) * 4;
    int y  = (strip >> 6) & 255;
    int b  = strip >> 14;

    float acc[4][4];
    #pragma unroll
    for (int ox = 0; ox < 4; ox++)
        #pragma unroll
        for (int e = 0; e < 4; e++) acc[ox][e] = 0.f;

    #pragma unroll
    for (int dy = -1; dy <= 1; dy++) {
        int yy = y + dy;
        if (yy < 0 || yy > 255) continue;
        const bf16* rowp = in + ((size_t)((b << 8) + yy) << 8) * QKV;
        float v[6][4];
        #pragma unroll
        for (int j = 0; j < 6; j++) {
            int xx = xs - 1 + j;
            if (xx >= 0 && xx <= 255) {
                uint2 u = *(const uint2*)(rowp + (size_t)xx * QKV + c4 * 4);
                float2 f0 = __bfloat1622float2(((const __nv_bfloat162*)&u)[0]);
                float2 f1 = __bfloat1622float2(((const __nv_bfloat162*)&u)[1]);
                v[j][0] = f0.x; v[j][1] = f0.y; v[j][2] = f1.x; v[j][3] = f1.y;
            } else {
                #pragma unroll
                for (int e = 0; e < 4; e++) v[j][e] = 0.f;
            }
        }
        #pragma unroll
        for (int dx = 0; dx < 3; dx++) {
            float4 kv = *(const float4*)(kern + (size_t)((dy + 1) * 3 + dx) * QKV + c4 * 4);
            float kk[4] = {kv.x, kv.y, kv.z, kv.w};
            #pragma unroll
            for (int ox = 0; ox < 4; ox++)
                #pragma unroll
                for (int e = 0; e < 4; e++) acc[ox][e] += v[ox + dx][e] * kk[e];
        }
    }
    bf16* op = out + ((size_t)((b << 16) + (y << 8) + xs)) * QKV + c4 * 4;
    #pragma unroll
    for (int ox = 0; ox < 4; ox++) {
        uint2 u;
        ((uint32_t*)&u)[0] = pack_bf2(acc[ox][0], acc[ox][1]);
        ((uint32_t*)&u)[1] = pack_bf2(acc[ox][2], acc[ox][3]);
        *(uint2*)(op + (size_t)ox * QKV) = u;
    }
}

// ---------------- q*k^T + fused norms: 128 px/block, double-buffered tiles ----------------
#define QKT_SPB 128
__global__ void qkt_kernel(const bf16* __restrict__ t1, float* __restrict__ attn,
                           float* __restrict__ nrm) {
    __shared__ float qs[2][16][48];
    __shared__ float ks[2][16][48];
    __shared__ float nq[48], nk[48];
    int bh = blockIdx.y;
    int b = bh >> 1, hd = bh & 1;
    int s0 = blockIdx.x * QKT_SPB;
    int tid = threadIdx.x;
    if (tid < 48) { nq[tid] = 0.f; nk[tid] = 0.f; }
    int tx = tid & 15, ty = tid >> 4;
    float acc[3][3];
    #pragma unroll
    for (int r = 0; r < 3; r++)
        #pragma unroll
        for (int c = 0; c < 3; c++) acc[r][c] = 0.f;
    float sqq[3] = {0.f, 0.f, 0.f}, sqk[3] = {0.f, 0.f, 0.f};

    const bf16* qbase = t1 + ((size_t)(b << 16)) * QKV + hd * CH;
    const bf16* kbase = qbase + CDIM;

    // per-thread load coords (3 elements)
    int lsi[3], le[3];
    #pragma unroll
    for (int l = 0; l < 3; l++) {
        int idx = tid + l * 256;
        lsi[l] = idx / 48; le[l] = idx % 48;
    }

    // preload tile 0
    #pragma unroll
    for (int l = 0; l < 3; l++) {
        size_t off = (size_t)(s0 + lsi[l]) * QKV + le[l];
        float qv = __bfloat162float(qbase[off]);
        float kv = __bfloat162float(kbase[off]);
        qs[0][lsi[l]][le[l]] = qv; ks[0][lsi[l]][le[l]] = kv;
        sqq[l] += qv * qv; sqk[l] += kv * kv;
    }
    __syncthreads();

    #pragma unroll 1
    for (int st = 0; st < QKT_SPB; st += 16) {
        int cur = (st >> 4) & 1;
        if (st + 16 < QKT_SPB) {
            int nb = cur ^ 1;
            #pragma unroll
            for (int l = 0; l < 3; l++) {
                size_t off = (size_t)(s0 + st + 16 + lsi[l]) * QKV + le[l];
                float qv = __bfloat162float(qbase[off]);
                float kv = __bfloat162float(kbase[off]);
                qs[nb][lsi[l]][le[l]] = qv; ks[nb][lsi[l]][le[l]] = kv;
                sqq[l] += qv * qv; sqk[l] += kv * kv;
            }
        }
        #pragma unroll
        for (int si = 0; si < 16; si++) {
            float qv[3], kv[3];
            #pragma unroll
            for (int r = 0; r < 3; r++) qv[r] = qs[cur][si][ty * 3 + r];
            #pragma unroll
            for (int c = 0; c < 3; c++) kv[c] = ks[cur][si][tx * 3 + c];
            #pragma unroll
            for (int r = 0; r < 3; r++)
                #pragma unroll
                for (int c = 0; c < 3; c++) acc[r][c] += qv[r] * kv[c];
        }
        __syncthreads();
    }
    #pragma unroll
    for (int l = 0; l < 3; l++) {
        atomicAdd(&nq[le[l]], sqq[l]);
        atomicAdd(&nk[le[l]], sqk[l]);
    }
    float* ab = attn + (size_t)bh * CH * CH;
    #pragma unroll
    for (int r = 0; r < 3; r++)
        #pragma unroll
        for (int c = 0; c < 3; c++)
            atomicAdd(&ab[(ty * 3 + r) * CH + (tx * 3 + c)], acc[r][c]);
    __syncthreads();
    if (tid < 48) {
        atomicAdd(&nrm[b * 192 + hd * CH + tid], nq[tid]);
        atomicAdd(&nrm[b * 192 + CDIM + hd * CH + tid], nk[tid]);
    }
}

// ---------------- normalize + temperature + softmax ----------------
__global__ void softmax_kernel(float* __restrict__ attn, const float* __restrict__ nrm,
                               const float* __restrict__ temp) {
    int bh = blockIdx.x;
    int b = bh >> 1, hd = bh & 1;
    int d = threadIdx.x;
    if (d >= CH) return;
    float t = temp[hd];
    float rq = rsqrtf(nrm[b * 192 + hd * CH + d]);
    float* row = attn + (size_t)bh * CH * CH + d * CH;
    float vals[CH];
    float mx = -1e30f;
    #pragma unroll
    for (int e = 0; e < CH; e++) {
        float rk = rsqrtf(nrm[b * 192 + CDIM + hd * CH + e]);
        float v = row[e] * rq * rk * t;
        vals[e] = v;
        mx = fmaxf(mx, v);
    }
    float s = 0.f;
    #pragma unroll
    for (int e = 0; e < CH; e++) { vals[e] = expf(vals[e] - mx); s += vals[e]; }
    float inv = 1.f / s;
    #pragma unroll
    for (int e = 0; e < CH; e++) row[e] = vals[e] * inv;
}

// ---------------- o = attn @ v (transposed attn in smem, conflict-free) ----------------
__global__ void attnapply_kernel(const bf16* __restrict__ t1, const float* __restrict__ attn,
                                 bf16* __restrict__ o) {
    __shared__ float at_t[CH][2 * CH + 4];
    __shared__ float vs[32][CDIM];
    int b = blockIdx.y;
    int p0 = blockIdx.x * 32;
    int tid = threadIdx.x;
    for (int i = tid; i < HEADS * CH * CH; i += 256) {
        int hd = i / (CH * CH);
        int rem = i - hd * CH * CH;
        int cm = rem / CH, e = rem % CH;
        at_t[e][hd * CH + cm] = attn[(size_t)b * HEADS * CH * CH + i];
    }
    const bf16* vbase = t1 + ((size_t)((b << 16) + p0)) * QKV + 2 * CDIM;
    #pragma unroll
    for (int l = 0; l < 6; l++) {
        int idx = tid + l * 256;
        int p = idx / 48, cu = idx % 48;
        uint32_t u = *(const uint32_t*)(vbase + (size_t)p * QKV + cu * 2);
        float2 f = __bfloat1622float2(*(__nv_bfloat162*)&u);
        vs[p][cu * 2] = f.x; vs[p][cu * 2 + 1] = f.y;
    }
    __syncthreads();
    bf16* obase = o + ((size_t)((b << 16) + p0)) * CDIM;
    #pragma unroll
    for (int l = 0; l < 12; l++) {
        int idx = tid + l * 256;
        int p = idx / CDIM, c = idx % CDIM;
        int hd = c / CH;
        const float* vrow = &vs[p][hd * CH];
        float s = 0.f;
        #pragma unroll
        for (int e = 0; e < CH; e++) s += at_t[e][c] * vrow[e];
        obase[(size_t)p * CDIM + c] = __float2bfloat16_rn(s);
    }
}

// ---------------- depthwise 3x3 + GELU gate: 512-col layout, 2ch x 4px ----------------
__global__ void dwgate_kernel(const bf16* __restrict__ in, const float* __restrict__ kwp,
                              bf16* __restrict__ out) {
    int idx = blockIdx.x * blockDim.x + threadIdx.x;
    int c2 = idx & 127;
    int strip = idx >> 7;
    int xs = (strip & 63) * 4;
    int y  = (strip >> 6) & 255;
    int b  = strip >> 14;

    float accA[4][2], accB[4][2];
    #pragma unroll
    for (int ox = 0; ox < 4; ox++) {
        accA[ox][0] = 0.f; accA[ox][1] = 0.f;
        accB[ox][0] = 0.f; accB[ox][1] = 0.f;
    }

    #pragma unroll
    for (int dy = -1; dy <= 1; dy++) {
        int yy = y + dy;
        if (yy < 0 || yy > 255) continue;
        const bf16* rowp = in + (((size_t)((b << 8) + yy) << 8) << 9);
        float va[6][2], vb[6][2];
        #pragma unroll
        for (int j = 0; j < 6; j++) {
            int xx = xs - 1 + j;
            if (xx >= 0 && xx <= 255) {
                const bf16* pp = rowp + ((size_t)xx << 9) + c2 * 2;
                uint32_t u1 = *(const uint32_t*)pp;
                uint32_t u2 = *(const uint32_t*)(pp + 256);
                float2 f1 = __bfloat1622float2(*(__nv_bfloat162*)&u1);
                float2 f2 = __bfloat1622float2(*(__nv_bfloat162*)&u2);
                va[j][0] = f1.x; va[j][1] = f1.y;
                vb[j][0] = f2.x; vb[j][1] = f2.y;
            } else {
                va[j][0] = 0.f; va[j][1] = 0.f;
                vb[j][0] = 0.f; vb[j][1] = 0.f;
            }
        }
        #pragma unroll
        for (int dx = 0; dx < 3; dx++) {
            int ki = (dy + 1) * 3 + dx;
            float2 k1 = *(const float2*)(kwp + ki * H2P + c2 * 2);
            float2 k2 = *(const float2*)(kwp + ki * H2P + 256 + c2 * 2);
            #pragma unroll
            for (int ox = 0; ox < 4; ox++) {
                accA[ox][0] += va[ox + dx][0] * k1.x;
                accA[ox][1] += va[ox + dx][1] * k1.y;
                accB[ox][0] += vb[ox + dx][0] * k2.x;
                accB[ox][1] += vb[ox + dx][1] * k2.y;
            }
        }
    }
    size_t pbase = (size_t)((b << 16) + (y << 8) + xs);
    #pragma unroll
    for (int ox = 0; ox < 4; ox++) {
        float g0 = gelu_exact(accA[ox][0]) * accB[ox][0];
        float g1 = gelu_exact(accA[ox][1]) * accB[ox][1];
        *(uint32_t*)(out + (pbase + ox) * HIDP + c2 * 2) = pack_bf2(g0, g1);
    }
}

// ---------------- launcher ----------------
extern "C" void kernel_launch(void* const* d_in, const int* in_sizes, int n_in,
                              void* d_out, int out_size) {
    const float* x     = (const float*)d_in[0];
    const float* ln1g  = (const float*)d_in[1];
    const float* ln1b  = (const float*)d_in[2];
    const float* ln2g  = (const float*)d_in[3];
    const float* ln2b  = (const float*)d_in[4];
    const float* qkvw  = (const float*)d_in[5];
    const float* qkvdw = (const float*)d_in[6];
    const float* temp  = (const float*)d_in[7];
    const float* aow   = (const float*)d_in[8];
    const float* fiw   = (const float*)d_in[9];
    const float* fdw   = (const float*)d_in[10];
    const float* fow   = (const float*)d_in[11];
    float* out = (float*)d_out;

    bf16 *t0, *t1, *t2, *gt, *ybf, *wq, *wa, *wip, *wo2;
    float *x2, *nrm, *att, *kwp;
    cudaGetSymbolAddress((void**)&t0,  g_t0);
    cudaGetSymbolAddress((void**)&t1,  g_t1);
    cudaGetSymbolAddress((void**)&t2,  g_t2);
    cudaGetSymbolAddress((void**)&gt,  g_gt);
    cudaGetSymbolAddress((void**)&ybf, g_ybf);
    cudaGetSymbolAddress((void**)&x2,  g_x2);
    cudaGetSymbolAddress((void**)&nrm, g_nrm);
    cudaGetSymbolAddress((void**)&att, g_att);
    cudaGetSymbolAddress((void**)&wq,  g_wq);
    cudaGetSymbolAddress((void**)&wa,  g_wa);
    cudaGetSymbolAddress((void**)&wip, g_wip);
    cudaGetSymbolAddress((void**)&wo2, g_wo2);
    cudaGetSymbolAddress((void**)&kwp, g_kwp);

    const int SMEM_FO = 2 * 128 * 72 * 2 + 256 * 104 * 2;            // 90112
    const int SMEM_QKV = 128 * 104 * 2 + 96 * (288 + 8) * 2;         // 83456
    const int SMEM_FFI = 128 * 104 * 2 + 96 * (256 + 8) * 2;         // 77312
    cudaFuncSetAttribute(gemm_ffnout, cudaFuncAttributeMaxDynamicSharedMemorySize, SMEM_FO);
    cudaFuncSetAttribute((gemm_bres<3, 6, true>),  cudaFuncAttributeMaxDynamicSharedMemorySize, SMEM_QKV);
    cudaFuncSetAttribute((gemm_bres<2, 8, false>), cudaFuncAttributeMaxDynamicSharedMemorySize, SMEM_FFI);

    const int cvt_total = CDIM * QKV + CDIM * CDIM + CDIM * H2P + HID * CDIM;
    cvt_all_kernel<<<(cvt_total + 255) / 256, 256>>>(qkvw, aow, fiw, fow, fdw,
                                                     wq, wa, wip, wo2, kwp, nrm, att);

    // attention branch: fused LN1 + qkv GEMM (B resident)
    gemm_bres<3, 6, true><<<dim3(1, 1024), 256, SMEM_QKV>>>(
        nullptr, x, ln1g, ln1b, wq, t0, QKV);
    dwconv288_kernel<<<(NPIX / 4) * 72 / 256, 256>>>(t0, qkvdw, t1);
    qkt_kernel<<<dim3(65536 / QKT_SPB, 4), 256>>>(t1, att, nrm);
    softmax_kernel<<<4, 64>>>(att, nrm, temp);
    attnapply_kernel<<<dim3(2048, 2), 256>>>(t1, att, ybf);
    // fused: x2 = ybf@wa + x ; ybf = LN2(x2)
    gemm_attnout_ln<<<1024, 256>>>(ybf, wa, x, x2, ybf, ln2g, ln2b);

    // FFN branch: B-resident ffn_in (2 column blocks of 256), remapped 512-col layout
    gemm_bres<2, 8, false><<<dim3(2, 1024), 256, SMEM_FFI>>>(
        ybf, nullptr, nullptr, nullptr, wip, t2, H2P);
    dwgate_kernel<<<(NPIX / 4) * 128 / 256, 256>>>(t2, kwp, gt);
    gemm_ffnout<<<1024, 256, SMEM_FO>>>(gt, wo2, x2, out);
}

// round 14
// speedup vs baseline: 1.0782x; 1.0782x over previous
#include <cuda_runtime.h>
#include <cuda_bf16.h>
#include <math.h>
#include <stdint.h>

// ---------------- problem constants ----------------
#define BATCH 2
#define CDIM 96
#define HEADS 2
#define CH 48
#define QKV 288
#define HID 255
#define HIDP 256
#define H2 510
#define H2P 512
#define NPIX 131072

typedef __nv_bfloat16 bf16;

// ---------------- device scratch ----------------
__device__ __align__(256) bf16 g_t0[(size_t)NPIX * QKV];
__device__ __align__(256) bf16 g_t1[(size_t)NPIX * QKV];
__device__ __align__(256) bf16 g_t2[(size_t)NPIX * H2P];
__device__ __align__(256) bf16 g_gt[(size_t)NPIX * HIDP];
__device__ __align__(256) bf16 g_ybf[(size_t)NPIX * CDIM];
__device__ __align__(256) float g_x2[(size_t)NPIX * CDIM];
__device__ float g_nrm[2 * BATCH * CDIM];
__device__ float g_att[BATCH * HEADS * CH * CH];
__device__ __align__(256) bf16 g_wq[CDIM * QKV];
__device__ __align__(256) bf16 g_wa[CDIM * CDIM];
__device__ __align__(256) bf16 g_wip[CDIM * H2P];
__device__ __align__(256) bf16 g_wo2[HIDP * CDIM];
__device__ __align__(256) float g_kwp[9 * H2P];

// ---------------- helpers ----------------
__device__ __forceinline__ float gelu_exact(float v) {
    return 0.5f * v * (1.0f + erff(v * 0.70710678118654752f));
}
__device__ __forceinline__ void ldsm_x4(uint32_t* r, uint32_t addr) {
    asm volatile("ldmatrix.sync.aligned.m8n8.x4.shared.b16 {%0,%1,%2,%3}, [%4];"
        : "=r"(r[0]), "=r"(r[1]), "=r"(r[2]), "=r"(r[3]) : "r"(addr));
}
__device__ __forceinline__ void ldsm_x4_t(uint32_t* r, uint32_t addr) {
    asm volatile("ldmatrix.sync.aligned.m8n8.x4.trans.shared.b16 {%0,%1,%2,%3}, [%4];"
        : "=r"(r[0]), "=r"(r[1]), "=r"(r[2]), "=r"(r[3]) : "r"(addr));
}
__device__ __forceinline__ void mma_bf16(float* c, const uint32_t* a, const uint32_t* b) {
    asm volatile("mma.sync.aligned.m16n8k16.row.col.f32.bf16.bf16.f32 "
        "{%0,%1,%2,%3}, {%4,%5,%6,%7}, {%8,%9}, {%0,%1,%2,%3};\n"
        : "+f"(c[0]), "+f"(c[1]), "+f"(c[2]), "+f"(c[3])
        : "r"(a[0]), "r"(a[1]), "r"(a[2]), "r"(a[3]), "r"(b[0]), "r"(b[1]));
}
__device__ __forceinline__ uint32_t pack_bf2(float a, float b) {
    __nv_bfloat162 h = __floats2bfloat162_rn(a, b);
    return *(uint32_t*)&h;
}
__device__ __forceinline__ void cp16(uint32_t dst, const void* src) {
    asm volatile("cp.async.ca.shared.global [%0], [%1], 16;" :: "r"(dst), "l"(src));
}
#define CP_COMMIT() asm volatile("cp.async.commit_group;")
__device__ __forceinline__ void cp_wait0() { asm volatile("cp.async.wait_group 0;"); }
__device__ __forceinline__ void cp_wait1() { asm volatile("cp.async.wait_group 1;"); }

// ---------------- weight convert / remap + accumulator init ----------------
__global__ void cvt_all_kernel(const float* wq, const float* wa, const float* wi, const float* wo,
                               const float* fdw,
                               bf16* dq, bf16* da, bf16* dip, bf16* dxo2,
                               float* kwp, float* nrm, float* attn) {
    int i = blockIdx.x * blockDim.x + threadIdx.x;
    const int s0 = CDIM * QKV, s1 = s0 + CDIM * CDIM;
    if (i < s0) dq[i] = __float2bfloat16_rn(wq[i]);
    else if (i < s1) da[i - s0] = __float2bfloat16_rn(wa[i - s0]);
    if (i < CDIM * H2P) {
        int r = i >> 9, c = i & 511;
        float v = 0.f;
        if (c < 255) v = wi[r * H2 + c];
        else if (c >= 256 && c <= 510) v = wi[r * H2 + c - 1];
        dip[i] = __float2bfloat16_rn(v);
    }
    if (i < HIDP * CDIM) {
        int r = i / CDIM;
        dxo2[i] = (r < HID) ? __float2bfloat16_rn(wo[i]) : __float2bfloat16_rn(0.f);
    }
    if (i < 9 * H2P) {
        int d = i >> 9, c = i & 511;
        float v = 0.f;
        if (c < 255) v = fdw[d * H2 + c];
        else if (c >= 256 && c <= 510) v = fdw[d * H2 + c - 1];
        kwp[i] = v;
    }
    if (i < 2 * BATCH * CDIM) nrm[i] = 0.f;
    if (i < BATCH * HEADS * CH * CH) attn[i] = 0.f;
}

// ---------------- generic B-resident GEMM, K=96, multi-pass N, optional fused LN on A ----------------
template<int NPASS, int NT, bool FUSE_LN>
__global__ void __launch_bounds__(256)
gemm_bres(const bf16* __restrict__ Abf, const float* __restrict__ Xf,
          const float* __restrict__ gamma, const float* __restrict__ beta,
          const bf16* __restrict__ Bw, bf16* __restrict__ Cout, int Nglob) {
    constexpr int PASSW = NT * 16;
    constexpr int BCOLS = NPASS * PASSW;
    constexpr int PA = 104;
    constexpr int PB = BCOLS + 8;
    extern __shared__ char smraw[];
    bf16* As = (bf16*)smraw;
    bf16* Bs = (bf16*)smraw + 128 * PA;
    uint32_t as_base = (uint32_t)__cvta_generic_to_shared(smraw);
    uint32_t bs_base = as_base + 128 * PA * 2;

    int tid = threadIdx.x, lane = tid & 31, warp = tid >> 5;
    int m0 = blockIdx.y * 128;
    int ncol0 = blockIdx.x * BCOLS;
    int g = lane >> 2, tg = lane & 3;
    int warpM = warp & 3, warpN = warp >> 2;
    int mbase = warpM * 32, nbase = warpN * (NT * 8);

    constexpr int BU = 96 * (BCOLS / 2);
    #pragma unroll
    for (int l = 0; l < BU / 256; l++) {
        int idx = tid + l * 256;
        int row = idx / (BCOLS / 2), nu = idx % (BCOLS / 2);
        *(uint32_t*)&Bs[row * PB + nu * 2] =
            *(const uint32_t*)(Bw + (size_t)row * Nglob + ncol0 + nu * 2);
    }

    if (FUSE_LN) {
        float ga0 = gamma[lane], ga1 = gamma[lane + 32], ga2 = gamma[lane + 64];
        float be0 = beta[lane],  be1 = beta[lane + 32],  be2 = beta[lane + 64];
        #pragma unroll
        for (int i = 0; i < 16; i++) {
            int row = warp * 16 + i;
            const float* xp = Xf + (size_t)(m0 + row) * CDIM;
            float v0 = xp[lane], v1 = xp[lane + 32], v2 = xp[lane + 64];
            float s  = v0 + v1 + v2;
            float ss = v0 * v0 + v1 * v1 + v2 * v2;
            #pragma unroll
            for (int o = 16; o > 0; o >>= 1) {
                s  += __shfl_xor_sync(0xffffffffu, s,  o);
                ss += __shfl_xor_sync(0xffffffffu, ss, o);
            }
            float mu = s * (1.f / 96.f);
            float var = ss * (1.f / 96.f) - mu * mu;
            float rstd = rsqrtf(var + 1e-5f);
            As[row * PA + lane]      = __float2bfloat16_rn((v0 - mu) * rstd * ga0 + be0);
            As[row * PA + lane + 32] = __float2bfloat16_rn((v1 - mu) * rstd * ga1 + be1);
            As[row * PA + lane + 64] = __float2bfloat16_rn((v2 - mu) * rstd * ga2 + be2);
        }
    } else {
        #pragma unroll
        for (int l = 0; l < 6; l++) {
            int idx = tid + l * 256;
            int row = idx / 12, c8 = idx % 12;
            *(uint4*)&As[row * PA + c8 * 8] =
                *(const uint4*)(Abf + (size_t)(m0 + row) * CDIM + c8 * 8);
        }
    }
    __syncthreads();

    uint32_t a_addr[2], b_addr0[NT / 2];
    {
        int arow = lane & 15, acol = (lane >> 4) << 3;
        a_addr[0] = as_base + (uint32_t)(((mbase + arow) * PA + acol) * 2);
        a_addr[1] = as_base + (uint32_t)(((mbase + 16 + arow) * PA + acol) * 2);
        int krow = ((lane >> 3) & 1) * 8 + (lane & 7);
        int coff = (lane >> 4) << 3;
        #pragma unroll
        for (int nh = 0; nh < NT / 2; nh++)
            b_addr0[nh] = bs_base + (uint32_t)((krow * PB + nbase + nh * 16 + coff) * 2);
    }

    #pragma unroll
    for (int pass = 0; pass < NPASS; pass++) {
        float acc[2][NT][4];
        #pragma unroll
        for (int mt = 0; mt < 2; mt++)
            #pragma unroll
            for (int nt = 0; nt < NT; nt++)
                #pragma unroll
                for (int i = 0; i < 4; i++) acc[mt][nt][i] = 0.f;

        uint32_t poff = (uint32_t)(pass * PASSW * 2);
        #pragma unroll
        for (int ks = 0; ks < 6; ks++) {
            uint32_t af[2][4];
            ldsm_x4(af[0], a_addr[0] + ks * 32);
            ldsm_x4(af[1], a_addr[1] + ks * 32);
            #pragma unroll
            for (int nh = 0; nh < NT / 2; nh++) {
                uint32_t bq[4];
                ldsm_x4_t(bq, b_addr0[nh] + poff + ks * 16 * (PB * 2));
                #pragma unroll
                for (int mt = 0; mt < 2; mt++) {
                    mma_bf16(acc[mt][nh * 2 + 0], af[mt], &bq[0]);
                    mma_bf16(acc[mt][nh * 2 + 1], af[mt], &bq[2]);
                }
            }
        }
        #pragma unroll
        for (int mt = 0; mt < 2; mt++) {
            #pragma unroll
            for (int nt = 0; nt < NT; nt++) {
                int col = ncol0 + pass * PASSW + nbase + nt * 8 + tg * 2;
                #pragma unroll
                for (int h = 0; h < 2; h++) {
                    int row = m0 + mbase + mt * 16 + g + h * 8;
                    size_t o = (size_t)row * Nglob + col;
                    *(uint32_t*)(Cout + o) = pack_bf2(acc[mt][nt][h * 2 + 0],
                                                      acc[mt][nt][h * 2 + 1]);
                }
            }
        }
    }
}

// ---------------- dedicated ffn_out GEMM: K=256 (padded), B resident, A pipelined ----------------
__global__ void __launch_bounds__(256)
gemm_ffnout(const bf16* __restrict__ A, const bf16* __restrict__ Bw,
            const float* __restrict__ R, float* __restrict__ C) {
    constexpr int PA = 72, PB = 104;
    constexpr int ABUF = 128 * PA * 2;
    extern __shared__ char smraw[];
    uint32_t as_base = (uint32_t)__cvta_generic_to_shared(smraw);
    uint32_t bs_base = as_base + 2 * ABUF;
    bf16* Bsm = (bf16*)(smraw + 2 * ABUF);

    int tid = threadIdx.x, lane = tid & 31, warp = tid >> 5;
    int m0 = blockIdx.x * 128;
    int g = lane >> 2, tg = lane & 3;
    int warpM = warp & 3, warpN = warp >> 2;
    int mbase = warpM * 32, nbase = warpN * 48;

    #pragma unroll
    for (int l = 0; l < 48; l++) {
        int idx = tid + l * 256;
        int row = idx / 48, nu = idx % 48;
        *(uint32_t*)&Bsm[row * PB + nu * 2] = *(const uint32_t*)(Bw + (size_t)row * CDIM + nu * 2);
    }

    uint32_t a_addr[2], b_addr[3];
    {
        int arow = lane & 15, acol = (lane >> 4) << 3;
        a_addr[0] = as_base + (uint32_t)(((mbase + arow) * PA + acol) * 2);
        a_addr[1] = as_base + (uint32_t)(((mbase + 16 + arow) * PA + acol) * 2);
        int krow = ((lane >> 3) & 1) * 8 + (lane & 7);
        int coff = (lane >> 4) << 3;
        #pragma unroll
        for (int nh = 0; nh < 3; nh++)
            b_addr[nh] = bs_base + (uint32_t)((krow * PB + nbase + nh * 16 + coff) * 2);
    }

    #pragma unroll
    for (int l = 0; l < 4; l++) {
        int idx = tid + l * 256;
        int row = idx >> 3, c8 = idx & 7;
        cp16(as_base + (uint32_t)((row * PA + c8 * 8) * 2),
             A + (size_t)(m0 + row) * HIDP + c8 * 8);
    }
    CP_COMMIT();

    float acc[2][6][4];
    #pragma unroll
    for (int a = 0; a < 2; a++)
        #pragma unroll
        for (int b = 0; b < 6; b++)
            #pragma unroll
            for (int c = 0; c < 4; c++) acc[a][b][c] = 0.f;

    int bufc = 0;
    #pragma unroll
    for (int kit = 0; kit < 4; kit++) {
        if (kit < 3) {
            int k0n = (kit + 1) * 64;
            uint32_t dstb = as_base + (uint32_t)((bufc ^ 1) * ABUF);
            #pragma unroll
            for (int l = 0; l < 4; l++) {
                int idx = tid + l * 256;
                int row = idx >> 3, c8 = idx & 7;
                cp16(dstb + (uint32_t)((row * PA + c8 * 8) * 2),
                     A + (size_t)(m0 + row) * HIDP + k0n + c8 * 8);
            }
            CP_COMMIT();
            cp_wait1();
        } else {
            cp_wait0();
        }
        __syncthreads();
        uint32_t abuf = (uint32_t)(bufc * ABUF);
        #pragma unroll
        for (int ks = 0; ks < 4; ks++) {
            uint32_t af[2][4];
            ldsm_x4(af[0], a_addr[0] + abuf + ks * 32);
            ldsm_x4(af[1], a_addr[1] + abuf + ks * 32);
            int kglob = kit * 64 + ks * 16;
            #pragma unroll
            for (int nh = 0; nh < 3; nh++) {
                uint32_t bq[4];
                ldsm_x4_t(bq, b_addr[nh] + kglob * (PB * 2));
                mma_bf16(acc[0][nh * 2 + 0], af[0], &bq[0]);
                mma_bf16(acc[0][nh * 2 + 1], af[0], &bq[2]);
                mma_bf16(acc[1][nh * 2 + 0], af[1], &bq[0]);
                mma_bf16(acc[1][nh * 2 + 1], af[1], &bq[2]);
            }
        }
        __syncthreads();
        bufc ^= 1;
    }

    #pragma unroll
    for (int mt = 0; mt < 2; mt++) {
        #pragma unroll
        for (int nt = 0; nt < 6; nt++) {
            int col = nbase + nt * 8 + tg * 2;
            #pragma unroll
            for (int h = 0; h < 2; h++) {
                int row = m0 + mbase + mt * 16 + g + h * 8;
                size_t o = (size_t)row * CDIM + col;
                float2 r2 = *(const float2*)(R + o);
                *(float2*)(C + o) = make_float2(acc[mt][nt][h * 2 + 0] + r2.x,
                                                acc[mt][nt][h * 2 + 1] + r2.y);
            }
        }
    }
}

// ---------------- attn_out GEMM (N=96, K=96) with fused residual + LayerNorm2 ----------------
__global__ void __launch_bounds__(256)
gemm_attnout_ln(const bf16* __restrict__ A, const bf16* __restrict__ Bw,
                const float* __restrict__ R, float* __restrict__ x2out,
                bf16* __restrict__ yout,
                const float* __restrict__ gamma, const float* __restrict__ beta) {
    constexpr int PA = 104, PB = 104;
    __shared__ __align__(16) char buf[49152];
    bf16* As = (bf16*)buf;
    bf16* Bs = (bf16*)buf + 128 * PA;

    int tid = threadIdx.x, lane = tid & 31, warp = tid >> 5;
    int m0 = blockIdx.x * 128;
    int g = lane >> 2, tg = lane & 3;
    int warpM = warp & 3, warpN = warp >> 2;
    int mbase = warpM * 32, nbase = warpN * 48;

    #pragma unroll
    for (int l = 0; l < 6; l++) {
        int idx = tid + l * 256;
        int row = idx / 12, c8 = idx % 12;
        *(uint4*)&As[row * PA + c8 * 8] = *(const uint4*)(A + (size_t)(m0 + row) * 96 + c8 * 8);
    }
    #pragma unroll
    for (int l = 0; l < 18; l++) {
        int idx = tid + l * 256;
        int row = idx / 48, nu = idx % 48;
        *(uint32_t*)&Bs[row * PB + nu * 2] = *(const uint32_t*)(Bw + (size_t)row * 96 + nu * 2);
    }
    __syncthreads();

    uint32_t a_addr[2], b_addr[3];
    {
        int arow = lane & 15, acol = (lane >> 4) << 3;
        #pragma unroll
        for (int mt = 0; mt < 2; mt++)
            a_addr[mt] = (uint32_t)__cvta_generic_to_shared(&As[(mbase + mt * 16 + arow) * PA + acol]);
        int krow = ((lane >> 3) & 1) * 8 + (lane & 7);
        int coff = (lane >> 4) << 3;
        #pragma unroll
        for (int nh = 0; nh < 3; nh++)
            b_addr[nh] = (uint32_t)__cvta_generic_to_shared(&Bs[krow * PB + nbase + nh * 16 + coff]);
    }

    float acc[2][6][4];
    #pragma unroll
    for (int mt = 0; mt < 2; mt++)
        #pragma unroll
        for (int nt = 0; nt < 6; nt++)
            #pragma unroll
            for (int i = 0; i < 4; i++) acc[mt][nt][i] = 0.f;

    #pragma unroll
    for (int ks = 0; ks < 6; ks++) {
        uint32_t af[2][4];
        ldsm_x4(af[0], a_addr[0] + ks * 32);
        ldsm_x4(af[1], a_addr[1] + ks * 32);
        #pragma unroll
        for (int nh = 0; nh < 3; nh++) {
            uint32_t bq[4];
            ldsm_x4_t(bq, b_addr[nh] + ks * 16 * (PB * 2));
            #pragma unroll
            for (int mt = 0; mt < 2; mt++) {
                mma_bf16(acc[mt][nh * 2 + 0], af[mt], &bq[0]);
                mma_bf16(acc[mt][nh * 2 + 1], af[mt], &bq[2]);
            }
        }
    }
    __syncthreads();

    float* sx = (float*)buf;
    #pragma unroll
    for (int mt = 0; mt < 2; mt++) {
        #pragma unroll
        for (int nt = 0; nt < 6; nt++) {
            int col = nbase + nt * 8 + tg * 2;
            #pragma unroll
            for (int h = 0; h < 2; h++) {
                int rl = mbase + mt * 16 + g + h * 8;
                size_t o = (size_t)(m0 + rl) * 96 + col;
                float2 r2 = *(const float2*)(R + o);
                float v0 = acc[mt][nt][h * 2 + 0] + r2.x;
                float v1 = acc[mt][nt][h * 2 + 1] + r2.y;
                *(float2*)(x2out + o) = make_float2(v0, v1);
                int t = (rl & 3) << 3;
                *(float2*)(sx + rl * 96 + (col ^ t)) = make_float2(v0, v1);
            }
        }
    }
    __syncthreads();

    float ga0 = gamma[lane], ga1 = gamma[lane + 32], ga2 = gamma[lane + 64];
    float be0 = beta[lane],  be1 = beta[lane + 32],  be2 = beta[lane + 64];
    #pragma unroll
    for (int i = 0; i < 16; i++) {
        int wr = warp * 16 + i;
        int t = (wr & 3) << 3;
        int c0 = lane ^ t;
        float v0 = sx[wr * 96 + c0];
        float v1 = sx[wr * 96 + c0 + 32];
        float v2 = sx[wr * 96 + c0 + 64];
        float s  = v0 + v1 + v2;
        float ss = v0 * v0 + v1 * v1 + v2 * v2;
        #pragma unroll
        for (int o = 16; o > 0; o >>= 1) {
            s  += __shfl_xor_sync(0xffffffffu, s,  o);
            ss += __shfl_xor_sync(0xffffffffu, ss, o);
        }
        float mu = s * (1.f / 96.f);
        float var = ss * (1.f / 96.f) - mu * mu;
        float rstd = rsqrtf(var + 1e-5f);
        bf16* yp = yout + (size_t)(m0 + wr) * 96;
        yp[lane]      = __float2bfloat16_rn((v0 - mu) * rstd * ga0 + be0);
        yp[lane + 32] = __float2bfloat16_rn((v1 - mu) * rstd * ga1 + be1);
        yp[lane + 64] = __float2bfloat16_rn((v2 - mu) * rstd * ga2 + be2);
    }
}

// ---------------- depthwise 3x3, C=288 bf16, 4-ch chunks, 4-wide x strip ----------------
__global__ void dwconv288_kernel(const bf16* __restrict__ in, const float* __restrict__ kern,
                                 bf16* __restrict__ out) {
    const int C4 = QKV / 4;
    int idx = blockIdx.x * blockDim.x + threadIdx.x;
    if (idx >= (NPIX / 4) * C4) return;
    int c4 = idx % C4;
    int strip = idx / C4;
    int xs = (strip & 63) * 4;
    int y  = (strip >> 6) & 255;
    int b  = strip >> 14;

    float acc[4][4];
    #pragma unroll
    for (int ox = 0; ox < 4; ox++)
        #pragma unroll
        for (int e = 0; e < 4; e++) acc[ox][e] = 0.f;

    #pragma unroll
    for (int dy = -1; dy <= 1; dy++) {
        int yy = y + dy;
        if (yy < 0 || yy > 255) continue;
        const bf16* rowp = in + ((size_t)((b << 8) + yy) << 8) * QKV;
        float v[6][4];
        #pragma unroll
        for (int j = 0; j < 6; j++) {
            int xx = xs - 1 + j;
            if (xx >= 0 && xx <= 255) {
                uint2 u = *(const uint2*)(rowp + (size_t)xx * QKV + c4 * 4);
                float2 f0 = __bfloat1622float2(((const __nv_bfloat162*)&u)[0]);
                float2 f1 = __bfloat1622float2(((const __nv_bfloat162*)&u)[1]);
                v[j][0] = f0.x; v[j][1] = f0.y; v[j][2] = f1.x; v[j][3] = f1.y;
            } else {
                #pragma unroll
                for (int e = 0; e < 4; e++) v[j][e] = 0.f;
            }
        }
        #pragma unroll
        for (int dx = 0; dx < 3; dx++) {
            float4 kv = *(const float4*)(kern + (size_t)((dy + 1) * 3 + dx) * QKV + c4 * 4);
            float kk[4] = {kv.x, kv.y, kv.z, kv.w};
            #pragma unroll
            for (int ox = 0; ox < 4; ox++)
                #pragma unroll
                for (int e = 0; e < 4; e++) acc[ox][e] += v[ox + dx][e] * kk[e];
        }
    }
    bf16* op = out + ((size_t)((b << 16) + (y << 8) + xs)) * QKV + c4 * 4;
    #pragma unroll
    for (int ox = 0; ox < 4; ox++) {
        uint2 u;
        ((uint32_t*)&u)[0] = pack_bf2(acc[ox][0], acc[ox][1]);
        ((uint32_t*)&u)[1] = pack_bf2(acc[ox][2], acc[ox][3]);
        *(uint2*)(op + (size_t)ox * QKV) = u;
    }
}

// ---------------- q*k^T via tensor-core MMA + fused q/k norms ----------------
// Grid (128, 4): block handles 512 pixels of one (b,hd) as 4 chunks of 128.
// smem [s][c] bf16 tiles; A via trans-ldmatrix (m=c from [k][m] storage), B via gemm pattern.
__global__ void __launch_bounds__(256)
qkt_kernel(const bf16* __restrict__ t1, float* __restrict__ attn, float* __restrict__ nrm) {
    __shared__ __align__(16) bf16 qs[128][56];
    __shared__ __align__(16) bf16 ks[128][56];
    __shared__ float satt[CH][CH];
    __shared__ float nq[48], nk[48];
    int bh = blockIdx.y;
    int b = bh >> 1, hd = bh & 1;
    int s0 = blockIdx.x * 512;
    int tid = threadIdx.x, lane = tid & 31, warp = tid >> 5;

    for (int i = tid; i < CH * CH; i += 256) ((float*)satt)[i] = 0.f;
    if (tid < 48) { nq[tid] = 0.f; nk[tid] = 0.f; }

    float acc[3][6][4];
    #pragma unroll
    for (int mt = 0; mt < 3; mt++)
        #pragma unroll
        for (int nt = 0; nt < 6; nt++)
            #pragma unroll
            for (int i = 0; i < 4; i++) acc[mt][nt][i] = 0.f;

    const bf16* qbase = t1 + ((size_t)(b << 16)) * QKV + hd * CH;

    // staging assignment: threads 0..191, fixed c4 per thread
    int sc4 = tid % 12, sgrp = tid / 12;       // sgrp 0..15 valid (tid<192)
    bool stager = (tid < 192);
    float nqa[4] = {0.f, 0.f, 0.f, 0.f}, nka[4] = {0.f, 0.f, 0.f, 0.f};

    uint32_t qs_base = (uint32_t)__cvta_generic_to_shared(&qs[0][0]);
    uint32_t ks_base = (uint32_t)__cvta_generic_to_shared(&ks[0][0]);
    // A (q) trans-ldmatrix address pattern: k=(lane&7)+((lane>>4)<<3), m=((lane>>3)&1)*8
    int a_k = (lane & 7) + ((lane >> 4) << 3);
    int a_m = ((lane >> 3) & 1) << 3;
    // B (k) pattern (same as gemm): k=((lane>>3)&1)*8+(lane&7), n=(lane>>4)*8
    int b_k = ((lane >> 3) & 1) * 8 + (lane & 7);
    int b_n = (lane >> 4) << 3;
    uint32_t a_addr = qs_base + (uint32_t)(((warp * 16 + a_k) * 56 + a_m) * 2);
    uint32_t b_addr = ks_base + (uint32_t)(((warp * 16 + b_k) * 56 + b_n) * 2);

    __syncthreads();

    #pragma unroll 1
    for (int ch = 0; ch < 4; ch++) {
        int sb = s0 + ch * 128;
        if (stager) {
            #pragma unroll
            for (int l = 0; l < 8; l++) {
                int s = sgrp * 8 + l;
                const bf16* qp = qbase + (size_t)(sb + s) * QKV + sc4 * 4;
                uint2 uq = *(const uint2*)qp;
                uint2 uk = *(const uint2*)(qp + CDIM);
                *(uint2*)&qs[s][sc4 * 4] = uq;
                *(uint2*)&ks[s][sc4 * 4] = uk;
                float2 q0 = __bfloat1622float2(((const __nv_bfloat162*)&uq)[0]);
                float2 q1 = __bfloat1622float2(((const __nv_bfloat162*)&uq)[1]);
                float2 k0 = __bfloat1622float2(((const __nv_bfloat162*)&uk)[0]);
                float2 k1 = __bfloat1622float2(((const __nv_bfloat162*)&uk)[1]);
                nqa[0] += q0.x * q0.x; nqa[1] += q0.y * q0.y;
                nqa[2] += q1.x * q1.x; nqa[3] += q1.y * q1.y;
                nka[0] += k0.x * k0.x; nka[1] += k0.y * k0.y;
                nka[2] += k1.x * k1.x; nka[3] += k1.y * k1.y;
            }
        }
        __syncthreads();
        uint32_t af[3][4];
        ldsm_x4_t(af[0], a_addr);
        ldsm_x4_t(af[1], a_addr + 32);      // m += 16 (bf16*2)
        ldsm_x4_t(af[2], a_addr + 64);
        #pragma unroll
        for (int nt3 = 0; nt3 < 3; nt3++) {
            uint32_t bq[4];
            ldsm_x4_t(bq, b_addr + nt3 * 32);
            #pragma unroll
            for (int mt = 0; mt < 3; mt++) {
                mma_bf16(acc[mt][nt3 * 2 + 0], af[mt], &bq[0]);
                mma_bf16(acc[mt][nt3 * 2 + 1], af[mt], &bq[2]);
            }
        }
        __syncthreads();
    }

    // reduce accumulators into smem
    int g = lane >> 2, tg = lane & 3;
    #pragma unroll
    for (int mt = 0; mt < 3; mt++)
        #pragma unroll
        for (int nt = 0; nt < 6; nt++)
            #pragma unroll
            for (int i = 0; i < 4; i++) {
                int row = mt * 16 + g + ((i >> 1) << 3);
                int col = nt * 8 + tg * 2 + (i & 1);
                atomicAdd(&satt[row][col], acc[mt][nt][i]);
            }
    if (stager) {
        #pragma unroll
        for (int e = 0; e < 4; e++) {
            atomicAdd(&nq[sc4 * 4 + e], nqa[e]);
            atomicAdd(&nk[sc4 * 4 + e], nka[e]);
        }
    }
    __syncthreads();
    float* ab = attn + (size_t)bh * CH * CH;
    for (int i = tid; i < CH * CH; i += 256) atomicAdd(&ab[i], ((float*)satt)[i]);
    if (tid < 48) {
        atomicAdd(&nrm[b * 192 + hd * CH + tid], nq[tid]);
        atomicAdd(&nrm[b * 192 + CDIM + hd * CH + tid], nk[tid]);
    }
}

// ---------------- normalize + temperature + softmax ----------------
__global__ void softmax_kernel(float* __restrict__ attn, const float* __restrict__ nrm,
                               const float* __restrict__ temp) {
    int bh = blockIdx.x;
    int b = bh >> 1, hd = bh & 1;
    int d = threadIdx.x;
    if (d >= CH) return;
    float t = temp[hd];
    float rq = rsqrtf(nrm[b * 192 + hd * CH + d]);
    float* row = attn + (size_t)bh * CH * CH + d * CH;
    float vals[CH];
    float mx = -1e30f;
    #pragma unroll
    for (int e = 0; e < CH; e++) {
        float rk = rsqrtf(nrm[b * 192 + CDIM + hd * CH + e]);
        float v = row[e] * rq * rk * t;
        vals[e] = v;
        mx = fmaxf(mx, v);
    }
    float s = 0.f;
    #pragma unroll
    for (int e = 0; e < CH; e++) { vals[e] = expf(vals[e] - mx); s += vals[e]; }
    float inv = 1.f / s;
    #pragma unroll
    for (int e = 0; e < CH; e++) row[e] = vals[e] * inv;
}

// ---------------- o = attn @ v (transposed attn in smem, conflict-free) ----------------
__global__ void attnapply_kernel(const bf16* __restrict__ t1, const float* __restrict__ attn,
                                 bf16* __restrict__ o) {
    __shared__ float at_t[CH][2 * CH + 4];
    __shared__ float vs[32][CDIM];
    int b = blockIdx.y;
    int p0 = blockIdx.x * 32;
    int tid = threadIdx.x;
    for (int i = tid; i < HEADS * CH * CH; i += 256) {
        int hd = i / (CH * CH);
        int rem = i - hd * CH * CH;
        int cm = rem / CH, e = rem % CH;
        at_t[e][hd * CH + cm] = attn[(size_t)b * HEADS * CH * CH + i];
    }
    const bf16* vbase = t1 + ((size_t)((b << 16) + p0)) * QKV + 2 * CDIM;
    #pragma unroll
    for (int l = 0; l < 6; l++) {
        int idx = tid + l * 256;
        int p = idx / 48, cu = idx % 48;
        uint32_t u = *(const uint32_t*)(vbase + (size_t)p * QKV + cu * 2);
        float2 f = __bfloat1622float2(*(__nv_bfloat162*)&u);
        vs[p][cu * 2] = f.x; vs[p][cu * 2 + 1] = f.y;
    }
    __syncthreads();
    bf16* obase = o + ((size_t)((b << 16) + p0)) * CDIM;
    #pragma unroll
    for (int l = 0; l < 12; l++) {
        int idx = tid + l * 256;
        int p = idx / CDIM, c = idx % CDIM;
        int hd = c / CH;
        const float* vrow = &vs[p][hd * CH];
        float s = 0.f;
        #pragma unroll
        for (int e = 0; e < CH; e++) s += at_t[e][c] * vrow[e];
        obase[(size_t)p * CDIM + c] = __float2bfloat16_rn(s);
    }
}

// ---------------- depthwise 3x3 + GELU gate: 512-col layout, 2ch x 4px ----------------
__global__ void dwgate_kernel(const bf16* __restrict__ in, const float* __restrict__ kwp,
                              bf16* __restrict__ out) {
    int idx = blockIdx.x * blockDim.x + threadIdx.x;
    int c2 = idx & 127;
    int strip = idx >> 7;
    int xs = (strip & 63) * 4;
    int y  = (strip >> 6) & 255;
    int b  = strip >> 14;

    float accA[4][2], accB[4][2];
    #pragma unroll
    for (int ox = 0; ox < 4; ox++) {
        accA[ox][0] = 0.f; accA[ox][1] = 0.f;
        accB[ox][0] = 0.f; accB[ox][1] = 0.f;
    }

    #pragma unroll
    for (int dy = -1; dy <= 1; dy++) {
        int yy = y + dy;
        if (yy < 0 || yy > 255) continue;
        const bf16* rowp = in + (((size_t)((b << 8) + yy) << 8) << 9);
        float va[6][2], vb[6][2];
        #pragma unroll
        for (int j = 0; j < 6; j++) {
            int xx = xs - 1 + j;
            if (xx >= 0 && xx <= 255) {
                const bf16* pp = rowp + ((size_t)xx << 9) + c2 * 2;
                uint32_t u1 = *(const uint32_t*)pp;
                uint32_t u2 = *(const uint32_t*)(pp + 256);
                float2 f1 = __bfloat1622float2(*(__nv_bfloat162*)&u1);
                float2 f2 = __bfloat1622float2(*(__nv_bfloat162*)&u2);
                va[j][0] = f1.x; va[j][1] = f1.y;
                vb[j][0] = f2.x; vb[j][1] = f2.y;
            } else {
                va[j][0] = 0.f; va[j][1] = 0.f;
                vb[j][0] = 0.f; vb[j][1] = 0.f;
            }
        }
        #pragma unroll
        for (int dx = 0; dx < 3; dx++) {
            int ki = (dy + 1) * 3 + dx;
            float2 k1 = *(const float2*)(kwp + ki * H2P + c2 * 2);
            float2 k2 = *(const float2*)(kwp + ki * H2P + 256 + c2 * 2);
            #pragma unroll
            for (int ox = 0; ox < 4; ox++) {
                accA[ox][0] += va[ox + dx][0] * k1.x;
                accA[ox][1] += va[ox + dx][1] * k1.y;
                accB[ox][0] += vb[ox + dx][0] * k2.x;
                accB[ox][1] += vb[ox + dx][1] * k2.y;
            }
        }
    }
    size_t pbase = (size_t)((b << 16) + (y << 8) + xs);
    #pragma unroll
    for (int ox = 0; ox < 4; ox++) {
        float g0 = gelu_exact(accA[ox][0]) * accB[ox][0];
        float g1 = gelu_exact(accA[ox][1]) * accB[ox][1];
        *(uint32_t*)(out + (pbase + ox) * HIDP + c2 * 2) = pack_bf2(g0, g1);
    }
}

// ---------------- launcher ----------------
extern "C" void kernel_launch(void* const* d_in, const int* in_sizes, int n_in,
                              void* d_out, int out_size) {
    const float* x     = (const float*)d_in[0];
    const float* ln1g  = (const float*)d_in[1];
    const float* ln1b  = (const float*)d_in[2];
    const float* ln2g  = (const float*)d_in[3];
    const float* ln2b  = (const float*)d_in[4];
    const float* qkvw  = (const float*)d_in[5];
    const float* qkvdw = (const float*)d_in[6];
    const float* temp  = (const float*)d_in[7];
    const float* aow   = (const float*)d_in[8];
    const float* fiw   = (const float*)d_in[9];
    const float* fdw   = (const float*)d_in[10];
    const float* fow   = (const float*)d_in[11];
    float* out = (float*)d_out;

    bf16 *t0, *t1, *t2, *gt, *ybf, *wq, *wa, *wip, *wo2;
    float *x2, *nrm, *att, *kwp;
    cudaGetSymbolAddress((void**)&t0,  g_t0);
    cudaGetSymbolAddress((void**)&t1,  g_t1);
    cudaGetSymbolAddress((void**)&t2,  g_t2);
    cudaGetSymbolAddress((void**)&gt,  g_gt);
    cudaGetSymbolAddress((void**)&ybf, g_ybf);
    cudaGetSymbolAddress((void**)&x2,  g_x2);
    cudaGetSymbolAddress((void**)&nrm, g_nrm);
    cudaGetSymbolAddress((void**)&att, g_att);
    cudaGetSymbolAddress((void**)&wq,  g_wq);
    cudaGetSymbolAddress((void**)&wa,  g_wa);
    cudaGetSymbolAddress((void**)&wip, g_wip);
    cudaGetSymbolAddress((void**)&wo2, g_wo2);
    cudaGetSymbolAddress((void**)&kwp, g_kwp);

    const int SMEM_FO = 2 * 128 * 72 * 2 + 256 * 104 * 2;            // 90112
    const int SMEM_QKV = 128 * 104 * 2 + 96 * (288 + 8) * 2;         // 83456
    const int SMEM_FFI = 128 * 104 * 2 + 96 * (256 + 8) * 2;         // 77312
    cudaFuncSetAttribute(gemm_ffnout, cudaFuncAttributeMaxDynamicSharedMemorySize, SMEM_FO);
    cudaFuncSetAttribute((gemm_bres<3, 6, true>),  cudaFuncAttributeMaxDynamicSharedMemorySize, SMEM_QKV);
    cudaFuncSetAttribute((gemm_bres<2, 8, false>), cudaFuncAttributeMaxDynamicSharedMemorySize, SMEM_FFI);

    const int cvt_total = CDIM * QKV + CDIM * CDIM + CDIM * H2P + HID * CDIM;
    cvt_all_kernel<<<(cvt_total + 255) / 256, 256>>>(qkvw, aow, fiw, fow, fdw,
                                                     wq, wa, wip, wo2, kwp, nrm, att);

    // attention branch: fused LN1 + qkv GEMM (B resident)
    gemm_bres<3, 6, true><<<dim3(1, 1024), 256, SMEM_QKV>>>(
        nullptr, x, ln1g, ln1b, wq, t0, QKV);
    dwconv288_kernel<<<(NPIX / 4) * 72 / 256, 256>>>(t0, qkvdw, t1);
    qkt_kernel<<<dim3(128, 4), 256>>>(t1, att, nrm);
    softmax_kernel<<<4, 64>>>(att, nrm, temp);
    attnapply_kernel<<<dim3(2048, 2), 256>>>(t1, att, ybf);
    // fused: x2 = ybf@wa + x ; ybf = LN2(x2)
    gemm_attnout_ln<<<1024, 256>>>(ybf, wa, x, x2, ybf, ln2g, ln2b);

    // FFN branch: B-resident ffn_in (2 column blocks of 256), remapped 512-col layout
    gemm_bres<2, 8, false><<<dim3(2, 1024), 256, SMEM_FFI>>>(
        ybf, nullptr, nullptr, nullptr, wip, t2, H2P);
    dwgate_kernel<<<(NPIX / 4) * 128 / 256, 256>>>(t2, kwp, gt);
    gemm_ffnout<<<1024, 256, SMEM_FO>>>(gt, wo2, x2, out);
}

// round 15
// speedup vs baseline: 1.3567x; 1.2583x over previous
#include <cuda_runtime.h>
#include <cuda_bf16.h>
#include <math.h>
#include <stdint.h>

// ---------------- problem constants ----------------
#define BATCH 2
#define CDIM 96
#define HEADS 2
#define CH 48
#define QKV 288
#define HID 255
#define HIDP 256
#define H2 510
#define H2P 512
#define NPIX 131072

typedef __nv_bfloat16 bf16;

// ---------------- device scratch ----------------
__device__ __align__(256) bf16 g_t0[(size_t)NPIX * QKV];
__device__ __align__(256) bf16 g_t1[(size_t)NPIX * QKV];
__device__ __align__(256) bf16 g_t2[(size_t)NPIX * H2P];
__device__ __align__(256) bf16 g_gt[(size_t)NPIX * HIDP];
__device__ __align__(256) bf16 g_ybf[(size_t)NPIX * CDIM];
__device__ __align__(256) float g_x2[(size_t)NPIX * CDIM];
__device__ float g_nrm[2 * BATCH * CDIM];
__device__ float g_att[BATCH * HEADS * CH * CH];
__device__ __align__(256) bf16 g_M[BATCH * CDIM * CDIM];   // fused attn@Wa per batch
__device__ __align__(256) bf16 g_wq[CDIM * QKV];
__device__ __align__(256) bf16 g_wip[CDIM * H2P];
__device__ __align__(256) bf16 g_wo2[HIDP * CDIM];
__device__ __align__(256) float g_kwp[9 * H2P];

// ---------------- helpers ----------------
__device__ __forceinline__ float gelu_exact(float v) {
    return 0.5f * v * (1.0f + erff(v * 0.70710678118654752f));
}
__device__ __forceinline__ void ldsm_x4(uint32_t* r, uint32_t addr) {
    asm volatile("ldmatrix.sync.aligned.m8n8.x4.shared.b16 {%0,%1,%2,%3}, [%4];"
        : "=r"(r[0]), "=r"(r[1]), "=r"(r[2]), "=r"(r[3]) : "r"(addr));
}
__device__ __forceinline__ void ldsm_x4_t(uint32_t* r, uint32_t addr) {
    asm volatile("ldmatrix.sync.aligned.m8n8.x4.trans.shared.b16 {%0,%1,%2,%3}, [%4];"
        : "=r"(r[0]), "=r"(r[1]), "=r"(r[2]), "=r"(r[3]) : "r"(addr));
}
__device__ __forceinline__ void mma_bf16(float* c, const uint32_t* a, const uint32_t* b) {
    asm volatile("mma.sync.aligned.m16n8k16.row.col.f32.bf16.bf16.f32 "
        "{%0,%1,%2,%3}, {%4,%5,%6,%7}, {%8,%9}, {%0,%1,%2,%3};\n"
        : "+f"(c[0]), "+f"(c[1]), "+f"(c[2]), "+f"(c[3])
        : "r"(a[0]), "r"(a[1]), "r"(a[2]), "r"(a[3]), "r"(b[0]), "r"(b[1]));
}
__device__ __forceinline__ uint32_t pack_bf2(float a, float b) {
    __nv_bfloat162 h = __floats2bfloat162_rn(a, b);
    return *(uint32_t*)&h;
}
__device__ __forceinline__ void cp16(uint32_t dst, const void* src) {
    asm volatile("cp.async.ca.shared.global [%0], [%1], 16;" :: "r"(dst), "l"(src));
}
#define CP_COMMIT() asm volatile("cp.async.commit_group;")
__device__ __forceinline__ void cp_wait0() { asm volatile("cp.async.wait_group 0;"); }
__device__ __forceinline__ void cp_wait1() { asm volatile("cp.async.wait_group 1;"); }

// ---------------- weight convert / remap + accumulator init ----------------
__global__ void cvt_all_kernel(const float* wq, const float* wi, const float* wo,
                               const float* fdw,
                               bf16* dq, bf16* dip, bf16* dxo2,
                               float* kwp, float* nrm, float* attn) {
    int i = blockIdx.x * blockDim.x + threadIdx.x;
    const int s0 = CDIM * QKV;
    if (i < s0) dq[i] = __float2bfloat16_rn(wq[i]);
    if (i < CDIM * H2P) {
        int r = i >> 9, c = i & 511;
        float v = 0.f;
        if (c < 255) v = wi[r * H2 + c];
        else if (c >= 256 && c <= 510) v = wi[r * H2 + c - 1];
        dip[i] = __float2bfloat16_rn(v);
    }
    if (i < HIDP * CDIM) {
        int r = i / CDIM;
        dxo2[i] = (r < HID) ? __float2bfloat16_rn(wo[i]) : __float2bfloat16_rn(0.f);
    }
    if (i < 9 * H2P) {
        int d = i >> 9, c = i & 511;
        float v = 0.f;
        if (c < 255) v = fdw[d * H2 + c];
        else if (c >= 256 && c <= 510) v = fdw[d * H2 + c - 1];
        kwp[i] = v;
    }
    if (i < 2 * BATCH * CDIM) nrm[i] = 0.f;
    if (i < BATCH * HEADS * CH * CH) attn[i] = 0.f;
}

// ---------------- generic B-resident GEMM, K=96, multi-pass N, optional fused LN on A ----------------
template<int NPASS, int NT, bool FUSE_LN>
__global__ void __launch_bounds__(256)
gemm_bres(const bf16* __restrict__ Abf, const float* __restrict__ Xf,
          const float* __restrict__ gamma, const float* __restrict__ beta,
          const bf16* __restrict__ Bw, bf16* __restrict__ Cout, int Nglob) {
    constexpr int PASSW = NT * 16;
    constexpr int BCOLS = NPASS * PASSW;
    constexpr int PA = 104;
    constexpr int PB = BCOLS + 8;
    extern __shared__ char smraw[];
    bf16* As = (bf16*)smraw;
    bf16* Bs = (bf16*)smraw + 128 * PA;
    uint32_t as_base = (uint32_t)__cvta_generic_to_shared(smraw);
    uint32_t bs_base = as_base + 128 * PA * 2;

    int tid = threadIdx.x, lane = tid & 31, warp = tid >> 5;
    int m0 = blockIdx.y * 128;
    int ncol0 = blockIdx.x * BCOLS;
    int g = lane >> 2, tg = lane & 3;
    int warpM = warp & 3, warpN = warp >> 2;
    int mbase = warpM * 32, nbase = warpN * (NT * 8);

    constexpr int BU = 96 * (BCOLS / 2);
    #pragma unroll
    for (int l = 0; l < BU / 256; l++) {
        int idx = tid + l * 256;
        int row = idx / (BCOLS / 2), nu = idx % (BCOLS / 2);
        *(uint32_t*)&Bs[row * PB + nu * 2] =
            *(const uint32_t*)(Bw + (size_t)row * Nglob + ncol0 + nu * 2);
    }

    if (FUSE_LN) {
        float ga0 = gamma[lane], ga1 = gamma[lane + 32], ga2 = gamma[lane + 64];
        float be0 = beta[lane],  be1 = beta[lane + 32],  be2 = beta[lane + 64];
        #pragma unroll
        for (int i = 0; i < 16; i++) {
            int row = warp * 16 + i;
            const float* xp = Xf + (size_t)(m0 + row) * CDIM;
            float v0 = xp[lane], v1 = xp[lane + 32], v2 = xp[lane + 64];
            float s  = v0 + v1 + v2;
            float ss = v0 * v0 + v1 * v1 + v2 * v2;
            #pragma unroll
            for (int o = 16; o > 0; o >>= 1) {
                s  += __shfl_xor_sync(0xffffffffu, s,  o);
                ss += __shfl_xor_sync(0xffffffffu, ss, o);
            }
            float mu = s * (1.f / 96.f);
            float var = ss * (1.f / 96.f) - mu * mu;
            float rstd = rsqrtf(var + 1e-5f);
            As[row * PA + lane]      = __float2bfloat16_rn((v0 - mu) * rstd * ga0 + be0);
            As[row * PA + lane + 32] = __float2bfloat16_rn((v1 - mu) * rstd * ga1 + be1);
            As[row * PA + lane + 64] = __float2bfloat16_rn((v2 - mu) * rstd * ga2 + be2);
        }
    } else {
        #pragma unroll
        for (int l = 0; l < 6; l++) {
            int idx = tid + l * 256;
            int row = idx / 12, c8 = idx % 12;
            *(uint4*)&As[row * PA + c8 * 8] =
                *(const uint4*)(Abf + (size_t)(m0 + row) * CDIM + c8 * 8);
        }
    }
    __syncthreads();

    uint32_t a_addr[2], b_addr0[NT / 2];
    {
        int arow = lane & 15, acol = (lane >> 4) << 3;
        a_addr[0] = as_base + (uint32_t)(((mbase + arow) * PA + acol) * 2);
        a_addr[1] = as_base + (uint32_t)(((mbase + 16 + arow) * PA + acol) * 2);
        int krow = ((lane >> 3) & 1) * 8 + (lane & 7);
        int coff = (lane >> 4) << 3;
        #pragma unroll
        for (int nh = 0; nh < NT / 2; nh++)
            b_addr0[nh] = bs_base + (uint32_t)((krow * PB + nbase + nh * 16 + coff) * 2);
    }

    #pragma unroll
    for (int pass = 0; pass < NPASS; pass++) {
        float acc[2][NT][4];
        #pragma unroll
        for (int mt = 0; mt < 2; mt++)
            #pragma unroll
            for (int nt = 0; nt < NT; nt++)
                #pragma unroll
                for (int i = 0; i < 4; i++) acc[mt][nt][i] = 0.f;

        uint32_t poff = (uint32_t)(pass * PASSW * 2);
        #pragma unroll
        for (int ks = 0; ks < 6; ks++) {
            uint32_t af[2][4];
            ldsm_x4(af[0], a_addr[0] + ks * 32);
            ldsm_x4(af[1], a_addr[1] + ks * 32);
            #pragma unroll
            for (int nh = 0; nh < NT / 2; nh++) {
                uint32_t bq[4];
                ldsm_x4_t(bq, b_addr0[nh] + poff + ks * 16 * (PB * 2));
                #pragma unroll
                for (int mt = 0; mt < 2; mt++) {
                    mma_bf16(acc[mt][nh * 2 + 0], af[mt], &bq[0]);
                    mma_bf16(acc[mt][nh * 2 + 1], af[mt], &bq[2]);
                }
            }
        }
        #pragma unroll
        for (int mt = 0; mt < 2; mt++) {
            #pragma unroll
            for (int nt = 0; nt < NT; nt++) {
                int col = ncol0 + pass * PASSW + nbase + nt * 8 + tg * 2;
                #pragma unroll
                for (int h = 0; h < 2; h++) {
                    int row = m0 + mbase + mt * 16 + g + h * 8;
                    size_t o = (size_t)row * Nglob + col;
                    *(uint32_t*)(Cout + o) = pack_bf2(acc[mt][nt][h * 2 + 0],
                                                      acc[mt][nt][h * 2 + 1]);
                }
            }
        }
    }
}

// ---------------- dedicated ffn_out GEMM: K=256 (padded), B resident, A pipelined ----------------
__global__ void __launch_bounds__(256)
gemm_ffnout(const bf16* __restrict__ A, const bf16* __restrict__ Bw,
            const float* __restrict__ R, float* __restrict__ C) {
    constexpr int PA = 72, PB = 104;
    constexpr int ABUF = 128 * PA * 2;
    extern __shared__ char smraw[];
    uint32_t as_base = (uint32_t)__cvta_generic_to_shared(smraw);
    uint32_t bs_base = as_base + 2 * ABUF;
    bf16* Bsm = (bf16*)(smraw + 2 * ABUF);

    int tid = threadIdx.x, lane = tid & 31, warp = tid >> 5;
    int m0 = blockIdx.x * 128;
    int g = lane >> 2, tg = lane & 3;
    int warpM = warp & 3, warpN = warp >> 2;
    int mbase = warpM * 32, nbase = warpN * 48;

    #pragma unroll
    for (int l = 0; l < 48; l++) {
        int idx = tid + l * 256;
        int row = idx / 48, nu = idx % 48;
        *(uint32_t*)&Bsm[row * PB + nu * 2] = *(const uint32_t*)(Bw + (size_t)row * CDIM + nu * 2);
    }

    uint32_t a_addr[2], b_addr[3];
    {
        int arow = lane & 15, acol = (lane >> 4) << 3;
        a_addr[0] = as_base + (uint32_t)(((mbase + arow) * PA + acol) * 2);
        a_addr[1] = as_base + (uint32_t)(((mbase + 16 + arow) * PA + acol) * 2);
        int krow = ((lane >> 3) & 1) * 8 + (lane & 7);
        int coff = (lane >> 4) << 3;
        #pragma unroll
        for (int nh = 0; nh < 3; nh++)
            b_addr[nh] = bs_base + (uint32_t)((krow * PB + nbase + nh * 16 + coff) * 2);
    }

    #pragma unroll
    for (int l = 0; l < 4; l++) {
        int idx = tid + l * 256;
        int row = idx >> 3, c8 = idx & 7;
        cp16(as_base + (uint32_t)((row * PA + c8 * 8) * 2),
             A + (size_t)(m0 + row) * HIDP + c8 * 8);
    }
    CP_COMMIT();

    float acc[2][6][4];
    #pragma unroll
    for (int a = 0; a < 2; a++)
        #pragma unroll
        for (int b = 0; b < 6; b++)
            #pragma unroll
            for (int c = 0; c < 4; c++) acc[a][b][c] = 0.f;

    int bufc = 0;
    #pragma unroll
    for (int kit = 0; kit < 4; kit++) {
        if (kit < 3) {
            int k0n = (kit + 1) * 64;
            uint32_t dstb = as_base + (uint32_t)((bufc ^ 1) * ABUF);
            #pragma unroll
            for (int l = 0; l < 4; l++) {
                int idx = tid + l * 256;
                int row = idx >> 3, c8 = idx & 7;
                cp16(dstb + (uint32_t)((row * PA + c8 * 8) * 2),
                     A + (size_t)(m0 + row) * HIDP + k0n + c8 * 8);
            }
            CP_COMMIT();
            cp_wait1();
        } else {
            cp_wait0();
        }
        __syncthreads();
        uint32_t abuf = (uint32_t)(bufc * ABUF);
        #pragma unroll
        for (int ks = 0; ks < 4; ks++) {
            uint32_t af[2][4];
            ldsm_x4(af[0], a_addr[0] + abuf + ks * 32);
            ldsm_x4(af[1], a_addr[1] + abuf + ks * 32);
            int kglob = kit * 64 + ks * 16;
            #pragma unroll
            for (int nh = 0; nh < 3; nh++) {
                uint32_t bq[4];
                ldsm_x4_t(bq, b_addr[nh] + kglob * (PB * 2));
                mma_bf16(acc[0][nh * 2 + 0], af[0], &bq[0]);
                mma_bf16(acc[0][nh * 2 + 1], af[0], &bq[2]);
                mma_bf16(acc[1][nh * 2 + 0], af[1], &bq[0]);
                mma_bf16(acc[1][nh * 2 + 1], af[1], &bq[2]);
            }
        }
        __syncthreads();
        bufc ^= 1;
    }

    #pragma unroll
    for (int mt = 0; mt < 2; mt++) {
        #pragma unroll
        for (int nt = 0; nt < 6; nt++) {
            int col = nbase + nt * 8 + tg * 2;
            #pragma unroll
            for (int h = 0; h < 2; h++) {
                int row = m0 + mbase + mt * 16 + g + h * 8;
                size_t o = (size_t)row * CDIM + col;
                float2 r2 = *(const float2*)(R + o);
                *(float2*)(C + o) = make_float2(acc[mt][nt][h * 2 + 0] + r2.x,
                                                acc[mt][nt][h * 2 + 1] + r2.y);
            }
        }
    }
}

// ---------------- fused attn-epilogue GEMM: x2 = V@M + x ; ybf = LN2(x2) ----------------
// A = v slice of t1 (offset 2*CDIM, row stride QKV); B = M[batch] (96x96 bf16).
__global__ void __launch_bounds__(256)
gemm_attnout_ln(const bf16* __restrict__ T1, const bf16* __restrict__ M,
                const float* __restrict__ R, float* __restrict__ x2out,
                bf16* __restrict__ yout,
                const float* __restrict__ gamma, const float* __restrict__ beta) {
    constexpr int PA = 104, PB = 104;
    __shared__ __align__(16) char buf[49152];
    bf16* As = (bf16*)buf;
    bf16* Bs = (bf16*)buf + 128 * PA;

    int tid = threadIdx.x, lane = tid & 31, warp = tid >> 5;
    int m0 = blockIdx.x * 128;
    int batch = blockIdx.x >> 9;           // 512 blocks per batch
    int g = lane >> 2, tg = lane & 3;
    int warpM = warp & 3, warpN = warp >> 2;
    int mbase = warpM * 32, nbase = warpN * 48;

    // A tile: v rows from t1 (row stride QKV, offset 2*CDIM)
    #pragma unroll
    for (int l = 0; l < 6; l++) {
        int idx = tid + l * 256;
        int row = idx / 12, c8 = idx % 12;
        *(uint4*)&As[row * PA + c8 * 8] =
            *(const uint4*)(T1 + (size_t)(m0 + row) * QKV + 2 * CDIM + c8 * 8);
    }
    // B = M[batch] (96x96 bf16)
    const bf16* Mb = M + (size_t)batch * 96 * 96;
    #pragma unroll
    for (int l = 0; l < 18; l++) {
        int idx = tid + l * 256;
        int row = idx / 48, nu = idx % 48;
        *(uint32_t*)&Bs[row * PB + nu * 2] = *(const uint32_t*)(Mb + (size_t)row * 96 + nu * 2);
    }
    __syncthreads();

    uint32_t a_addr[2], b_addr[3];
    {
        int arow = lane & 15, acol = (lane >> 4) << 3;
        #pragma unroll
        for (int mt = 0; mt < 2; mt++)
            a_addr[mt] = (uint32_t)__cvta_generic_to_shared(&As[(mbase + mt * 16 + arow) * PA + acol]);
        int krow = ((lane >> 3) & 1) * 8 + (lane & 7);
        int coff = (lane >> 4) << 3;
        #pragma unroll
        for (int nh = 0; nh < 3; nh++)
            b_addr[nh] = (uint32_t)__cvta_generic_to_shared(&Bs[krow * PB + nbase + nh * 16 + coff]);
    }

    float acc[2][6][4];
    #pragma unroll
    for (int mt = 0; mt < 2; mt++)
        #pragma unroll
        for (int nt = 0; nt < 6; nt++)
            #pragma unroll
            for (int i = 0; i < 4; i++) acc[mt][nt][i] = 0.f;

    #pragma unroll
    for (int ks = 0; ks < 6; ks++) {
        uint32_t af[2][4];
        ldsm_x4(af[0], a_addr[0] + ks * 32);
        ldsm_x4(af[1], a_addr[1] + ks * 32);
        #pragma unroll
        for (int nh = 0; nh < 3; nh++) {
            uint32_t bq[4];
            ldsm_x4_t(bq, b_addr[nh] + ks * 16 * (PB * 2));
            #pragma unroll
            for (int mt = 0; mt < 2; mt++) {
                mma_bf16(acc[mt][nh * 2 + 0], af[mt], &bq[0]);
                mma_bf16(acc[mt][nh * 2 + 1], af[mt], &bq[2]);
            }
        }
    }
    __syncthreads();

    float* sx = (float*)buf;
    #pragma unroll
    for (int mt = 0; mt < 2; mt++) {
        #pragma unroll
        for (int nt = 0; nt < 6; nt++) {
            int col = nbase + nt * 8 + tg * 2;
            #pragma unroll
            for (int h = 0; h < 2; h++) {
                int rl = mbase + mt * 16 + g + h * 8;
                size_t o = (size_t)(m0 + rl) * 96 + col;
                float2 r2 = *(const float2*)(R + o);
                float v0 = acc[mt][nt][h * 2 + 0] + r2.x;
                float v1 = acc[mt][nt][h * 2 + 1] + r2.y;
                *(float2*)(x2out + o) = make_float2(v0, v1);
                int t = (rl & 3) << 3;
                *(float2*)(sx + rl * 96 + (col ^ t)) = make_float2(v0, v1);
            }
        }
    }
    __syncthreads();

    float ga0 = gamma[lane], ga1 = gamma[lane + 32], ga2 = gamma[lane + 64];
    float be0 = beta[lane],  be1 = beta[lane + 32],  be2 = beta[lane + 64];
    #pragma unroll
    for (int i = 0; i < 16; i++) {
        int wr = warp * 16 + i;
        int t = (wr & 3) << 3;
        int c0 = lane ^ t;
        float v0 = sx[wr * 96 + c0];
        float v1 = sx[wr * 96 + c0 + 32];
        float v2 = sx[wr * 96 + c0 + 64];
        float s  = v0 + v1 + v2;
        float ss = v0 * v0 + v1 * v1 + v2 * v2;
        #pragma unroll
        for (int o = 16; o > 0; o >>= 1) {
            s  += __shfl_xor_sync(0xffffffffu, s,  o);
            ss += __shfl_xor_sync(0xffffffffu, ss, o);
        }
        float mu = s * (1.f / 96.f);
        float var = ss * (1.f / 96.f) - mu * mu;
        float rstd = rsqrtf(var + 1e-5f);
        bf16* yp = yout + (size_t)(m0 + wr) * 96;
        yp[lane]      = __float2bfloat16_rn((v0 - mu) * rstd * ga0 + be0);
        yp[lane + 32] = __float2bfloat16_rn((v1 - mu) * rstd * ga1 + be1);
        yp[lane + 64] = __float2bfloat16_rn((v2 - mu) * rstd * ga2 + be2);
    }
}

// ---------------- depthwise 3x3, C=288 bf16, 4-ch chunks, 4-wide x strip ----------------
__global__ void dwconv288_kernel(const bf16* __restrict__ in, const float* __restrict__ kern,
                                 bf16* __restrict__ out) {
    const int C4 = QKV / 4;
    int idx = blockIdx.x * blockDim.x + threadIdx.x;
    if (idx >= (NPIX / 4) * C4) return;
    int c4 = idx % C4;
    int strip = idx / C4;
    int xs = (strip & 63) * 4;
    int y  = (strip >> 6) & 255;
    int b  = strip >> 14;

    float acc[4][4];
    #pragma unroll
    for (int ox = 0; ox < 4; ox++)
        #pragma unroll
        for (int e = 0; e < 4; e++) acc[ox][e] = 0.f;

    #pragma unroll
    for (int dy = -1; dy <= 1; dy++) {
        int yy = y + dy;
        if (yy < 0 || yy > 255) continue;
        const bf16* rowp = in + ((size_t)((b << 8) + yy) << 8) * QKV;
        float v[6][4];
        #pragma unroll
        for (int j = 0; j < 6; j++) {
            int xx = xs - 1 + j;
            if (xx >= 0 && xx <= 255) {
                uint2 u = *(const uint2*)(rowp + (size_t)xx * QKV + c4 * 4);
                float2 f0 = __bfloat1622float2(((const __nv_bfloat162*)&u)[0]);
                float2 f1 = __bfloat1622float2(((const __nv_bfloat162*)&u)[1]);
                v[j][0] = f0.x; v[j][1] = f0.y; v[j][2] = f1.x; v[j][3] = f1.y;
            } else {
                #pragma unroll
                for (int e = 0; e < 4; e++) v[j][e] = 0.f;
            }
        }
        #pragma unroll
        for (int dx = 0; dx < 3; dx++) {
            float4 kv = *(const float4*)(kern + (size_t)((dy + 1) * 3 + dx) * QKV + c4 * 4);
            float kk[4] = {kv.x, kv.y, kv.z, kv.w};
            #pragma unroll
            for (int ox = 0; ox < 4; ox++)
                #pragma unroll
                for (int e = 0; e < 4; e++) acc[ox][e] += v[ox + dx][e] * kk[e];
        }
    }
    bf16* op = out + ((size_t)((b << 16) + (y << 8) + xs)) * QKV + c4 * 4;
    #pragma unroll
    for (int ox = 0; ox < 4; ox++) {
        uint2 u;
        ((uint32_t*)&u)[0] = pack_bf2(acc[ox][0], acc[ox][1]);
        ((uint32_t*)&u)[1] = pack_bf2(acc[ox][2], acc[ox][3]);
        *(uint2*)(op + (size_t)ox * QKV) = u;
    }
}

// ---------------- q*k^T via tensor-core MMA + fused q/k norms ----------------
__global__ void __launch_bounds__(256)
qkt_kernel(const bf16* __restrict__ t1, float* __restrict__ attn, float* __restrict__ nrm) {
    __shared__ __align__(16) bf16 qs[128][56];
    __shared__ __align__(16) bf16 ks[128][56];
    __shared__ float satt[CH][CH];
    __shared__ float nq[48], nk[48];
    int bh = blockIdx.y;
    int b = bh >> 1, hd = bh & 1;
    int s0 = blockIdx.x * 512;
    int tid = threadIdx.x, lane = tid & 31, warp = tid >> 5;

    for (int i = tid; i < CH * CH; i += 256) ((float*)satt)[i] = 0.f;
    if (tid < 48) { nq[tid] = 0.f; nk[tid] = 0.f; }

    float acc[3][6][4];
    #pragma unroll
    for (int mt = 0; mt < 3; mt++)
        #pragma unroll
        for (int nt = 0; nt < 6; nt++)
            #pragma unroll
            for (int i = 0; i < 4; i++) acc[mt][nt][i] = 0.f;

    const bf16* qbase = t1 + ((size_t)(b << 16)) * QKV + hd * CH;

    int sc4 = tid % 12, sgrp = tid / 12;
    bool stager = (tid < 192);
    float nqa[4] = {0.f, 0.f, 0.f, 0.f}, nka[4] = {0.f, 0.f, 0.f, 0.f};

    uint32_t qs_base = (uint32_t)__cvta_generic_to_shared(&qs[0][0]);
    uint32_t ks_base = (uint32_t)__cvta_generic_to_shared(&ks[0][0]);
    int a_k = (lane & 7) + ((lane >> 4) << 3);
    int a_m = ((lane >> 3) & 1) << 3;
    int b_k = ((lane >> 3) & 1) * 8 + (lane & 7);
    int b_n = (lane >> 4) << 3;
    uint32_t a_addr = qs_base + (uint32_t)(((warp * 16 + a_k) * 56 + a_m) * 2);
    uint32_t b_addr = ks_base + (uint32_t)(((warp * 16 + b_k) * 56 + b_n) * 2);

    __syncthreads();

    #pragma unroll 1
    for (int ch = 0; ch < 4; ch++) {
        int sb = s0 + ch * 128;
        if (stager) {
            #pragma unroll
            for (int l = 0; l < 8; l++) {
                int s = sgrp * 8 + l;
                const bf16* qp = qbase + (size_t)(sb + s) * QKV + sc4 * 4;
                uint2 uq = *(const uint2*)qp;
                uint2 uk = *(const uint2*)(qp + CDIM);
                *(uint2*)&qs[s][sc4 * 4] = uq;
                *(uint2*)&ks[s][sc4 * 4] = uk;
                float2 q0 = __bfloat1622float2(((const __nv_bfloat162*)&uq)[0]);
                float2 q1 = __bfloat1622float2(((const __nv_bfloat162*)&uq)[1]);
                float2 k0 = __bfloat1622float2(((const __nv_bfloat162*)&uk)[0]);
                float2 k1 = __bfloat1622float2(((const __nv_bfloat162*)&uk)[1]);
                nqa[0] += q0.x * q0.x; nqa[1] += q0.y * q0.y;
                nqa[2] += q1.x * q1.x; nqa[3] += q1.y * q1.y;
                nka[0] += k0.x * k0.x; nka[1] += k0.y * k0.y;
                nka[2] += k1.x * k1.x; nka[3] += k1.y * k1.y;
            }
        }
        __syncthreads();
        uint32_t af[3][4];
        ldsm_x4_t(af[0], a_addr);
        ldsm_x4_t(af[1], a_addr + 32);
        ldsm_x4_t(af[2], a_addr + 64);
        #pragma unroll
        for (int nt3 = 0; nt3 < 3; nt3++) {
            uint32_t bq[4];
            ldsm_x4_t(bq, b_addr + nt3 * 32);
            #pragma unroll
            for (int mt = 0; mt < 3; mt++) {
                mma_bf16(acc[mt][nt3 * 2 + 0], af[mt], &bq[0]);
                mma_bf16(acc[mt][nt3 * 2 + 1], af[mt], &bq[2]);
            }
        }
        __syncthreads();
    }

    int g = lane >> 2, tg = lane & 3;
    #pragma unroll
    for (int mt = 0; mt < 3; mt++)
        #pragma unroll
        for (int nt = 0; nt < 6; nt++)
            #pragma unroll
            for (int i = 0; i < 4; i++) {
                int row = mt * 16 + g + ((i >> 1) << 3);
                int col = nt * 8 + tg * 2 + (i & 1);
                atomicAdd(&satt[row][col], acc[mt][nt][i]);
            }
    if (stager) {
        #pragma unroll
        for (int e = 0; e < 4; e++) {
            atomicAdd(&nq[sc4 * 4 + e], nqa[e]);
            atomicAdd(&nk[sc4 * 4 + e], nka[e]);
        }
    }
    __syncthreads();
    float* ab = attn + (size_t)bh * CH * CH;
    for (int i = tid; i < CH * CH; i += 256) atomicAdd(&ab[i], ((float*)satt)[i]);
    if (tid < 48) {
        atomicAdd(&nrm[b * 192 + hd * CH + tid], nq[tid]);
        atomicAdd(&nrm[b * 192 + CDIM + hd * CH + tid], nk[tid]);
    }
}

// ---------------- softmax + fold attention into Wa: M[b, hd*48+e, d] ----------------
__global__ void softmax_fuse_kernel(const float* __restrict__ attn, const float* __restrict__ nrm,
                                    const float* __restrict__ temp, const float* __restrict__ wa,
                                    bf16* __restrict__ M) {
    __shared__ float sa[CH][CH];   // softmaxed rows
    int bh = blockIdx.x;
    int b = bh >> 1, hd = bh & 1;
    int tid = threadIdx.x;
    if (tid < CH) {
        int d = tid;
        float t = temp[hd];
        float rq = rsqrtf(nrm[b * 192 + hd * CH + d]);
        const float* row = attn + (size_t)bh * CH * CH + d * CH;
        float vals[CH];
        float mx = -1e30f;
        #pragma unroll
        for (int e = 0; e < CH; e++) {
            float rk = rsqrtf(nrm[b * 192 + CDIM + hd * CH + e]);
            float v = row[e] * rq * rk * t;
            vals[e] = v;
            mx = fmaxf(mx, v);
        }
        float s = 0.f;
        #pragma unroll
        for (int e = 0; e < CH; e++) { vals[e] = expf(vals[e] - mx); s += vals[e]; }
        float inv = 1.f / s;
        #pragma unroll
        for (int e = 0; e < CH; e++) sa[d][e] = vals[e] * inv;
    }
    __syncthreads();
    // M[b][hd*48+e][d] = sum_cm sa[cm][e] * wa[(hd*48+cm)*96 + d]
    for (int i = tid; i < CH * CDIM; i += 256) {
        int e = i / CDIM, d = i % CDIM;
        float s = 0.f;
        #pragma unroll
        for (int cm = 0; cm < CH; cm++)
            s += sa[cm][e] * wa[(size_t)(hd * CH + cm) * CDIM + d];
        M[((size_t)b * CDIM + hd * CH + e) * CDIM + d] = __float2bfloat16_rn(s);
    }
}

// ---------------- depthwise 3x3 + GELU gate: 512-col layout, 2ch x 4px ----------------
__global__ void dwgate_kernel(const bf16* __restrict__ in, const float* __restrict__ kwp,
                              bf16* __restrict__ out) {
    int idx = blockIdx.x * blockDim.x + threadIdx.x;
    int c2 = idx & 127;
    int strip = idx >> 7;
    int xs = (strip & 63) * 4;
    int y  = (strip >> 6) & 255;
    int b  = strip >> 14;

    float accA[4][2], accB[4][2];
    #pragma unroll
    for (int ox = 0; ox < 4; ox++) {
        accA[ox][0] = 0.f; accA[ox][1] = 0.f;
        accB[ox][0] = 0.f; accB[ox][1] = 0.f;
    }

    #pragma unroll
    for (int dy = -1; dy <= 1; dy++) {
        int yy = y + dy;
        if (yy < 0 || yy > 255) continue;
        const bf16* rowp = in + (((size_t)((b << 8) + yy) << 8) << 9);
        float va[6][2], vb[6][2];
        #pragma unroll
        for (int j = 0; j < 6; j++) {
            int xx = xs - 1 + j;
            if (xx >= 0 && xx <= 255) {
                const bf16* pp = rowp + ((size_t)xx << 9) + c2 * 2;
                uint32_t u1 = *(const uint32_t*)pp;
                uint32_t u2 = *(const uint32_t*)(pp + 256);
                float2 f1 = __bfloat1622float2(*(__nv_bfloat162*)&u1);
                float2 f2 = __bfloat1622float2(*(__nv_bfloat162*)&u2);
                va[j][0] = f1.x; va[j][1] = f1.y;
                vb[j][0] = f2.x; vb[j][1] = f2.y;
            } else {
                va[j][0] = 0.f; va[j][1] = 0.f;
                vb[j][0] = 0.f; vb[j][1] = 0.f;
            }
        }
        #pragma unroll
        for (int dx = 0; dx < 3; dx++) {
            int ki = (dy + 1) * 3 + dx;
            float2 k1 = *(const float2*)(kwp + ki * H2P + c2 * 2);
            float2 k2 = *(const float2*)(kwp + ki * H2P + 256 + c2 * 2);
            #pragma unroll
            for (int ox = 0; ox < 4; ox++) {
                accA[ox][0] += va[ox + dx][0] * k1.x;
                accA[ox][1] += va[ox + dx][1] * k1.y;
                accB[ox][0] += vb[ox + dx][0] * k2.x;
                accB[ox][1] += vb[ox + dx][1] * k2.y;
            }
        }
    }
    size_t pbase = (size_t)((b << 16) + (y << 8) + xs);
    #pragma unroll
    for (int ox = 0; ox < 4; ox++) {
        float g0 = gelu_exact(accA[ox][0]) * accB[ox][0];
        float g1 = gelu_exact(accA[ox][1]) * accB[ox][1];
        *(uint32_t*)(out + (pbase + ox) * HIDP + c2 * 2) = pack_bf2(g0, g1);
    }
}

// ---------------- launcher ----------------
extern "C" void kernel_launch(void* const* d_in, const int* in_sizes, int n_in,
                              void* d_out, int out_size) {
    const float* x     = (const float*)d_in[0];
    const float* ln1g  = (const float*)d_in[1];
    const float* ln1b  = (const float*)d_in[2];
    const float* ln2g  = (const float*)d_in[3];
    const float* ln2b  = (const float*)d_in[4];
    const float* qkvw  = (const float*)d_in[5];
    const float* qkvdw = (const float*)d_in[6];
    const float* temp  = (const float*)d_in[7];
    const float* aow   = (const float*)d_in[8];
    const float* fiw   = (const float*)d_in[9];
    const float* fdw   = (const float*)d_in[10];
    const float* fow   = (const float*)d_in[11];
    float* out = (float*)d_out;

    bf16 *t0, *t1, *t2, *gt, *ybf, *wq, *wip, *wo2, *M;
    float *x2, *nrm, *att, *kwp;
    cudaGetSymbolAddress((void**)&t0,  g_t0);
    cudaGetSymbolAddress((void**)&t1,  g_t1);
    cudaGetSymbolAddress((void**)&t2,  g_t2);
    cudaGetSymbolAddress((void**)&gt,  g_gt);
    cudaGetSymbolAddress((void**)&ybf, g_ybf);
    cudaGetSymbolAddress((void**)&x2,  g_x2);
    cudaGetSymbolAddress((void**)&nrm, g_nrm);
    cudaGetSymbolAddress((void**)&att, g_att);
    cudaGetSymbolAddress((void**)&M,   g_M);
    cudaGetSymbolAddress((void**)&wq,  g_wq);
    cudaGetSymbolAddress((void**)&wip, g_wip);
    cudaGetSymbolAddress((void**)&wo2, g_wo2);
    cudaGetSymbolAddress((void**)&kwp, g_kwp);

    const int SMEM_FO = 2 * 128 * 72 * 2 + 256 * 104 * 2;            // 90112
    const int SMEM_QKV = 128 * 104 * 2 + 96 * (288 + 8) * 2;         // 83456
    const int SMEM_FFI = 128 * 104 * 2 + 96 * (256 + 8) * 2;         // 77312
    cudaFuncSetAttribute(gemm_ffnout, cudaFuncAttributeMaxDynamicSharedMemorySize, SMEM_FO);
    cudaFuncSetAttribute((gemm_bres<3, 6, true>),  cudaFuncAttributeMaxDynamicSharedMemorySize, SMEM_QKV);
    cudaFuncSetAttribute((gemm_bres<2, 8, false>), cudaFuncAttributeMaxDynamicSharedMemorySize, SMEM_FFI);

    const int cvt_total = CDIM * QKV + CDIM * H2P;
    cvt_all_kernel<<<(cvt_total + 255) / 256, 256>>>(qkvw, fiw, fow, fdw,
                                                     wq, wip, wo2, kwp, nrm, att);

    // attention branch: fused LN1 + qkv GEMM (B resident)
    gemm_bres<3, 6, true><<<dim3(1, 1024), 256, SMEM_QKV>>>(
        nullptr, x, ln1g, ln1b, wq, t0, QKV);
    dwconv288_kernel<<<(NPIX / 4) * 72 / 256, 256>>>(t0, qkvdw, t1);
    qkt_kernel<<<dim3(128, 4), 256>>>(t1, att, nrm);
    softmax_fuse_kernel<<<4, 256>>>(att, nrm, temp, aow, M);
    // fused: x2 = v@M + x ; ybf = LN2(x2)   (attnapply folded into M)
    gemm_attnout_ln<<<1024, 256>>>(t1, M, x, x2, ybf, ln2g, ln2b);

    // FFN branch: B-resident ffn_in (2 column blocks of 256), remapped 512-col layout
    gemm_bres<2, 8, false><<<dim3(2, 1024), 256, SMEM_FFI>>>(
        ybf, nullptr, nullptr, nullptr, wip, t2, H2P);
    dwgate_kernel<<<(NPIX / 4) * 128 / 256, 256>>>(t2, kwp, gt);
    gemm_ffnout<<<1024, 256, SMEM_FO>>>(gt, wo2, x2, out);
}

// round 16
// speedup vs baseline: 1.3633x; 1.0049x over previous
#include <cuda_runtime.h>
#include <cuda_bf16.h>
#include <math.h>
#include <stdint.h>

// ---------------- problem constants ----------------
#define BATCH 2
#define CDIM 96
#define HEADS 2
#define CH 48
#define QKV 288
#define HID 255
#define HIDP 256
#define H2 510
#define H2P 512
#define NPIX 131072

typedef __nv_bfloat16 bf16;

// ---------------- device scratch ----------------
__device__ __align__(256) bf16 g_t0[(size_t)NPIX * QKV];
__device__ __align__(256) bf16 g_t1[(size_t)NPIX * QKV];
__device__ __align__(256) bf16 g_t2[(size_t)NPIX * H2P];
__device__ __align__(256) bf16 g_gt[(size_t)NPIX * HIDP];
__device__ __align__(256) bf16 g_ybf[(size_t)NPIX * CDIM];
__device__ __align__(256) float g_x2[(size_t)NPIX * CDIM];
__device__ float g_nrm[2 * BATCH * CDIM];
__device__ float g_att[BATCH * HEADS * CH * CH];
__device__ __align__(256) bf16 g_M[BATCH * CDIM * CDIM];
__device__ __align__(256) bf16 g_wq[CDIM * QKV];
__device__ __align__(256) bf16 g_wip[CDIM * H2P];
__device__ __align__(256) bf16 g_wo2[HIDP * CDIM];
__device__ __align__(256) float g_kwp[9 * H2P];

// ---------------- helpers ----------------
__device__ __forceinline__ float gelu_exact(float v) {
    return 0.5f * v * (1.0f + erff(v * 0.70710678118654752f));
}
__device__ __forceinline__ void ldsm_x4(uint32_t* r, uint32_t addr) {
    asm volatile("ldmatrix.sync.aligned.m8n8.x4.shared.b16 {%0,%1,%2,%3}, [%4];"
        : "=r"(r[0]), "=r"(r[1]), "=r"(r[2]), "=r"(r[3]) : "r"(addr));
}
__device__ __forceinline__ void ldsm_x4_t(uint32_t* r, uint32_t addr) {
    asm volatile("ldmatrix.sync.aligned.m8n8.x4.trans.shared.b16 {%0,%1,%2,%3}, [%4];"
        : "=r"(r[0]), "=r"(r[1]), "=r"(r[2]), "=r"(r[3]) : "r"(addr));
}
__device__ __forceinline__ void ldsm_x2_t(uint32_t* r, uint32_t addr) {
    asm volatile("ldmatrix.sync.aligned.m8n8.x2.trans.shared.b16 {%0,%1}, [%2];"
        : "=r"(r[0]), "=r"(r[1]) : "r"(addr));
}
__device__ __forceinline__ void mma_bf16(float* c, const uint32_t* a, const uint32_t* b) {
    asm volatile("mma.sync.aligned.m16n8k16.row.col.f32.bf16.bf16.f32 "
        "{%0,%1,%2,%3}, {%4,%5,%6,%7}, {%8,%9}, {%0,%1,%2,%3};\n"
        : "+f"(c[0]), "+f"(c[1]), "+f"(c[2]), "+f"(c[3])
        : "r"(a[0]), "r"(a[1]), "r"(a[2]), "r"(a[3]), "r"(b[0]), "r"(b[1]));
}
__device__ __forceinline__ uint32_t pack_bf2(float a, float b) {
    __nv_bfloat162 h = __floats2bfloat162_rn(a, b);
    return *(uint32_t*)&h;
}
__device__ __forceinline__ void cp16(uint32_t dst, const void* src) {
    asm volatile("cp.async.ca.shared.global [%0], [%1], 16;" :: "r"(dst), "l"(src));
}
#define CP_COMMIT() asm volatile("cp.async.commit_group;")
__device__ __forceinline__ void cp_wait0() { asm volatile("cp.async.wait_group 0;"); }
__device__ __forceinline__ void cp_wait1() { asm volatile("cp.async.wait_group 1;"); }

// ---------------- weight convert / remap + accumulator init ----------------
__global__ void cvt_all_kernel(const float* wq, const float* wi, const float* wo,
                               const float* fdw,
                               bf16* dq, bf16* dip, bf16* dxo2,
                               float* kwp, float* nrm, float* attn) {
    int i = blockIdx.x * blockDim.x + threadIdx.x;
    const int s0 = CDIM * QKV;
    if (i < s0) dq[i] = __float2bfloat16_rn(wq[i]);
    if (i < CDIM * H2P) {
        int r = i >> 9, c = i & 511;
        float v = 0.f;
        if (c < 255) v = wi[r * H2 + c];
        else if (c >= 256 && c <= 510) v = wi[r * H2 + c - 1];
        dip[i] = __float2bfloat16_rn(v);
    }
    if (i < HIDP * CDIM) {
        int r = i / CDIM;
        dxo2[i] = (r < HID) ? __float2bfloat16_rn(wo[i]) : __float2bfloat16_rn(0.f);
    }
    if (i < 9 * H2P) {
        int d = i >> 9, c = i & 511;
        float v = 0.f;
        if (c < 255) v = fdw[d * H2 + c];
        else if (c >= 256 && c <= 510) v = fdw[d * H2 + c - 1];
        kwp[i] = v;
    }
    if (i < 2 * BATCH * CDIM) nrm[i] = 0.f;
    if (i < BATCH * HEADS * CH * CH) attn[i] = 0.f;
}

// ---------------- generic B-resident GEMM, K=96, multi-pass N, optional fused LN on A ----------------
template<int NPASS, int NT, bool FUSE_LN>
__global__ void __launch_bounds__(256)
gemm_bres(const bf16* __restrict__ Abf, const float* __restrict__ Xf,
          const float* __restrict__ gamma, const float* __restrict__ beta,
          const bf16* __restrict__ Bw, bf16* __restrict__ Cout, int Nglob) {
    constexpr int PASSW = NT * 16;
    constexpr int BCOLS = NPASS * PASSW;
    constexpr int PA = 104;
    constexpr int PB = BCOLS + 8;
    extern __shared__ char smraw[];
    bf16* As = (bf16*)smraw;
    bf16* Bs = (bf16*)smraw + 128 * PA;
    uint32_t as_base = (uint32_t)__cvta_generic_to_shared(smraw);
    uint32_t bs_base = as_base + 128 * PA * 2;

    int tid = threadIdx.x, lane = tid & 31, warp = tid >> 5;
    int m0 = blockIdx.y * 128;
    int ncol0 = blockIdx.x * BCOLS;
    int g = lane >> 2, tg = lane & 3;
    int warpM = warp & 3, warpN = warp >> 2;
    int mbase = warpM * 32, nbase = warpN * (NT * 8);

    constexpr int BU = 96 * (BCOLS / 2);
    #pragma unroll
    for (int l = 0; l < BU / 256; l++) {
        int idx = tid + l * 256;
        int row = idx / (BCOLS / 2), nu = idx % (BCOLS / 2);
        *(uint32_t*)&Bs[row * PB + nu * 2] =
            *(const uint32_t*)(Bw + (size_t)row * Nglob + ncol0 + nu * 2);
    }

    if (FUSE_LN) {
        float ga0 = gamma[lane], ga1 = gamma[lane + 32], ga2 = gamma[lane + 64];
        float be0 = beta[lane],  be1 = beta[lane + 32],  be2 = beta[lane + 64];
        #pragma unroll
        for (int i = 0; i < 16; i++) {
            int row = warp * 16 + i;
            const float* xp = Xf + (size_t)(m0 + row) * CDIM;
            float v0 = xp[lane], v1 = xp[lane + 32], v2 = xp[lane + 64];
            float s  = v0 + v1 + v2;
            float ss = v0 * v0 + v1 * v1 + v2 * v2;
            #pragma unroll
            for (int o = 16; o > 0; o >>= 1) {
                s  += __shfl_xor_sync(0xffffffffu, s,  o);
                ss += __shfl_xor_sync(0xffffffffu, ss, o);
            }
            float mu = s * (1.f / 96.f);
            float var = ss * (1.f / 96.f) - mu * mu;
            float rstd = rsqrtf(var + 1e-5f);
            As[row * PA + lane]      = __float2bfloat16_rn((v0 - mu) * rstd * ga0 + be0);
            As[row * PA + lane + 32] = __float2bfloat16_rn((v1 - mu) * rstd * ga1 + be1);
            As[row * PA + lane + 64] = __float2bfloat16_rn((v2 - mu) * rstd * ga2 + be2);
        }
    } else {
        #pragma unroll
        for (int l = 0; l < 6; l++) {
            int idx = tid + l * 256;
            int row = idx / 12, c8 = idx % 12;
            *(uint4*)&As[row * PA + c8 * 8] =
                *(const uint4*)(Abf + (size_t)(m0 + row) * CDIM + c8 * 8);
        }
    }
    __syncthreads();

    uint32_t a_addr[2], b_addr0[NT / 2];
    {
        int arow = lane & 15, acol = (lane >> 4) << 3;
        a_addr[0] = as_base + (uint32_t)(((mbase + arow) * PA + acol) * 2);
        a_addr[1] = as_base + (uint32_t)(((mbase + 16 + arow) * PA + acol) * 2);
        int krow = ((lane >> 3) & 1) * 8 + (lane & 7);
        int coff = (lane >> 4) << 3;
        #pragma unroll
        for (int nh = 0; nh < NT / 2; nh++)
            b_addr0[nh] = bs_base + (uint32_t)((krow * PB + nbase + nh * 16 + coff) * 2);
    }

    #pragma unroll
    for (int pass = 0; pass < NPASS; pass++) {
        float acc[2][NT][4];
        #pragma unroll
        for (int mt = 0; mt < 2; mt++)
            #pragma unroll
            for (int nt = 0; nt < NT; nt++)
                #pragma unroll
                for (int i = 0; i < 4; i++) acc[mt][nt][i] = 0.f;

        uint32_t poff = (uint32_t)(pass * PASSW * 2);
        #pragma unroll
        for (int ks = 0; ks < 6; ks++) {
            uint32_t af[2][4];
            ldsm_x4(af[0], a_addr[0] + ks * 32);
            ldsm_x4(af[1], a_addr[1] + ks * 32);
            #pragma unroll
            for (int nh = 0; nh < NT / 2; nh++) {
                uint32_t bq[4];
                ldsm_x4_t(bq, b_addr0[nh] + poff + ks * 16 * (PB * 2));
                #pragma unroll
                for (int mt = 0; mt < 2; mt++) {
                    mma_bf16(acc[mt][nh * 2 + 0], af[mt], &bq[0]);
                    mma_bf16(acc[mt][nh * 2 + 1], af[mt], &bq[2]);
                }
            }
        }
        #pragma unroll
        for (int mt = 0; mt < 2; mt++) {
            #pragma unroll
            for (int nt = 0; nt < NT; nt++) {
                int col = ncol0 + pass * PASSW + nbase + nt * 8 + tg * 2;
                #pragma unroll
                for (int h = 0; h < 2; h++) {
                    int row = m0 + mbase + mt * 16 + g + h * 8;
                    size_t o = (size_t)row * Nglob + col;
                    *(uint32_t*)(Cout + o) = pack_bf2(acc[mt][nt][h * 2 + 0],
                                                      acc[mt][nt][h * 2 + 1]);
                }
            }
        }
    }
}

// ---------------- dedicated ffn_out GEMM: K=256 (padded), B resident, A pipelined ----------------
__global__ void __launch_bounds__(256)
gemm_ffnout(const bf16* __restrict__ A, const bf16* __restrict__ Bw,
            const float* __restrict__ R, float* __restrict__ C) {
    constexpr int PA = 72, PB = 104;
    constexpr int ABUF = 128 * PA * 2;
    extern __shared__ char smraw[];
    uint32_t as_base = (uint32_t)__cvta_generic_to_shared(smraw);
    uint32_t bs_base = as_base + 2 * ABUF;
    bf16* Bsm = (bf16*)(smraw + 2 * ABUF);

    int tid = threadIdx.x, lane = tid & 31, warp = tid >> 5;
    int m0 = blockIdx.x * 128;
    int g = lane >> 2, tg = lane & 3;
    int warpM = warp & 3, warpN = warp >> 2;
    int mbase = warpM * 32, nbase = warpN * 48;

    #pragma unroll
    for (int l = 0; l < 48; l++) {
        int idx = tid + l * 256;
        int row = idx / 48, nu = idx % 48;
        *(uint32_t*)&Bsm[row * PB + nu * 2] = *(const uint32_t*)(Bw + (size_t)row * CDIM + nu * 2);
    }

    uint32_t a_addr[2], b_addr[3];
    {
        int arow = lane & 15, acol = (lane >> 4) << 3;
        a_addr[0] = as_base + (uint32_t)(((mbase + arow) * PA + acol) * 2);
        a_addr[1] = as_base + (uint32_t)(((mbase + 16 + arow) * PA + acol) * 2);
        int krow = ((lane >> 3) & 1) * 8 + (lane & 7);
        int coff = (lane >> 4) << 3;
        #pragma unroll
        for (int nh = 0; nh < 3; nh++)
            b_addr[nh] = bs_base + (uint32_t)((krow * PB + nbase + nh * 16 + coff) * 2);
    }

    #pragma unroll
    for (int l = 0; l < 4; l++) {
        int idx = tid + l * 256;
        int row = idx >> 3, c8 = idx & 7;
        cp16(as_base + (uint32_t)((row * PA + c8 * 8) * 2),
             A + (size_t)(m0 + row) * HIDP + c8 * 8);
    }
    CP_COMMIT();

    float acc[2][6][4];
    #pragma unroll
    for (int a = 0; a < 2; a++)
        #pragma unroll
        for (int b = 0; b < 6; b++)
            #pragma unroll
            for (int c = 0; c < 4; c++) acc[a][b][c] = 0.f;

    int bufc = 0;
    #pragma unroll
    for (int kit = 0; kit < 4; kit++) {
        if (kit < 3) {
            int k0n = (kit + 1) * 64;
            uint32_t dstb = as_base + (uint32_t)((bufc ^ 1) * ABUF);
            #pragma unroll
            for (int l = 0; l < 4; l++) {
                int idx = tid + l * 256;
                int row = idx >> 3, c8 = idx & 7;
                cp16(dstb + (uint32_t)((row * PA + c8 * 8) * 2),
                     A + (size_t)(m0 + row) * HIDP + k0n + c8 * 8);
            }
            CP_COMMIT();
            cp_wait1();
        } else {
            cp_wait0();
        }
        __syncthreads();
        uint32_t abuf = (uint32_t)(bufc * ABUF);
        #pragma unroll
        for (int ks = 0; ks < 4; ks++) {
            uint32_t af[2][4];
            ldsm_x4(af[0], a_addr[0] + abuf + ks * 32);
            ldsm_x4(af[1], a_addr[1] + abuf + ks * 32);
            int kglob = kit * 64 + ks * 16;
            #pragma unroll
            for (int nh = 0; nh < 3; nh++) {
                uint32_t bq[4];
                ldsm_x4_t(bq, b_addr[nh] + kglob * (PB * 2));
                mma_bf16(acc[0][nh * 2 + 0], af[0], &bq[0]);
                mma_bf16(acc[0][nh * 2 + 1], af[0], &bq[2]);
                mma_bf16(acc[1][nh * 2 + 0], af[1], &bq[0]);
                mma_bf16(acc[1][nh * 2 + 1], af[1], &bq[2]);
            }
        }
        __syncthreads();
        bufc ^= 1;
    }

    #pragma unroll
    for (int mt = 0; mt < 2; mt++) {
        #pragma unroll
        for (int nt = 0; nt < 6; nt++) {
            int col = nbase + nt * 8 + tg * 2;
            #pragma unroll
            for (int h = 0; h < 2; h++) {
                int row = m0 + mbase + mt * 16 + g + h * 8;
                size_t o = (size_t)row * CDIM + col;
                float2 r2 = *(const float2*)(R + o);
                *(float2*)(C + o) = make_float2(acc[mt][nt][h * 2 + 0] + r2.x,
                                                acc[mt][nt][h * 2 + 1] + r2.y);
            }
        }
    }
}

// ---------------- fused attn-epilogue GEMM: x2 = V@M + x ; ybf = LN2(x2) ----------------
__global__ void __launch_bounds__(256)
gemm_attnout_ln(const bf16* __restrict__ T1, const bf16* __restrict__ M,
                const float* __restrict__ R, float* __restrict__ x2out,
                bf16* __restrict__ yout,
                const float* __restrict__ gamma, const float* __restrict__ beta) {
    constexpr int PA = 104, PB = 104;
    __shared__ __align__(16) char buf[49152];
    bf16* As = (bf16*)buf;
    bf16* Bs = (bf16*)buf + 128 * PA;

    int tid = threadIdx.x, lane = tid & 31, warp = tid >> 5;
    int m0 = blockIdx.x * 128;
    int batch = blockIdx.x >> 9;
    int g = lane >> 2, tg = lane & 3;
    int warpM = warp & 3, warpN = warp >> 2;
    int mbase = warpM * 32, nbase = warpN * 48;

    #pragma unroll
    for (int l = 0; l < 6; l++) {
        int idx = tid + l * 256;
        int row = idx / 12, c8 = idx % 12;
        *(uint4*)&As[row * PA + c8 * 8] =
            *(const uint4*)(T1 + (size_t)(m0 + row) * QKV + 2 * CDIM + c8 * 8);
    }
    const bf16* Mb = M + (size_t)batch * 96 * 96;
    #pragma unroll
    for (int l = 0; l < 18; l++) {
        int idx = tid + l * 256;
        int row = idx / 48, nu = idx % 48;
        *(uint32_t*)&Bs[row * PB + nu * 2] = *(const uint32_t*)(Mb + (size_t)row * 96 + nu * 2);
    }
    __syncthreads();

    uint32_t a_addr[2], b_addr[3];
    {
        int arow = lane & 15, acol = (lane >> 4) << 3;
        #pragma unroll
        for (int mt = 0; mt < 2; mt++)
            a_addr[mt] = (uint32_t)__cvta_generic_to_shared(&As[(mbase + mt * 16 + arow) * PA + acol]);
        int krow = ((lane >> 3) & 1) * 8 + (lane & 7);
        int coff = (lane >> 4) << 3;
        #pragma unroll
        for (int nh = 0; nh < 3; nh++)
            b_addr[nh] = (uint32_t)__cvta_generic_to_shared(&Bs[krow * PB + nbase + nh * 16 + coff]);
    }

    float acc[2][6][4];
    #pragma unroll
    for (int mt = 0; mt < 2; mt++)
        #pragma unroll
        for (int nt = 0; nt < 6; nt++)
            #pragma unroll
            for (int i = 0; i < 4; i++) acc[mt][nt][i] = 0.f;

    #pragma unroll
    for (int ks = 0; ks < 6; ks++) {
        uint32_t af[2][4];
        ldsm_x4(af[0], a_addr[0] + ks * 32);
        ldsm_x4(af[1], a_addr[1] + ks * 32);
        #pragma unroll
        for (int nh = 0; nh < 3; nh++) {
            uint32_t bq[4];
            ldsm_x4_t(bq, b_addr[nh] + ks * 16 * (PB * 2));
            #pragma unroll
            for (int mt = 0; mt < 2; mt++) {
                mma_bf16(acc[mt][nh * 2 + 0], af[mt], &bq[0]);
                mma_bf16(acc[mt][nh * 2 + 1], af[mt], &bq[2]);
            }
        }
    }
    __syncthreads();

    float* sx = (float*)buf;
    #pragma unroll
    for (int mt = 0; mt < 2; mt++) {
        #pragma unroll
        for (int nt = 0; nt < 6; nt++) {
            int col = nbase + nt * 8 + tg * 2;
            #pragma unroll
            for (int h = 0; h < 2; h++) {
                int rl = mbase + mt * 16 + g + h * 8;
                size_t o = (size_t)(m0 + rl) * 96 + col;
                float2 r2 = *(const float2*)(R + o);
                float v0 = acc[mt][nt][h * 2 + 0] + r2.x;
                float v1 = acc[mt][nt][h * 2 + 1] + r2.y;
                *(float2*)(x2out + o) = make_float2(v0, v1);
                int t = (rl & 3) << 3;
                *(float2*)(sx + rl * 96 + (col ^ t)) = make_float2(v0, v1);
            }
        }
    }
    __syncthreads();

    float ga0 = gamma[lane], ga1 = gamma[lane + 32], ga2 = gamma[lane + 64];
    float be0 = beta[lane],  be1 = beta[lane + 32],  be2 = beta[lane + 64];
    #pragma unroll
    for (int i = 0; i < 16; i++) {
        int wr = warp * 16 + i;
        int t = (wr & 3) << 3;
        int c0 = lane ^ t;
        float v0 = sx[wr * 96 + c0];
        float v1 = sx[wr * 96 + c0 + 32];
        float v2 = sx[wr * 96 + c0 + 64];
        float s  = v0 + v1 + v2;
        float ss = v0 * v0 + v1 * v1 + v2 * v2;
        #pragma unroll
        for (int o = 16; o > 0; o >>= 1) {
            s  += __shfl_xor_sync(0xffffffffu, s,  o);
            ss += __shfl_xor_sync(0xffffffffu, ss, o);
        }
        float mu = s * (1.f / 96.f);
        float var = ss * (1.f / 96.f) - mu * mu;
        float rstd = rsqrtf(var + 1e-5f);
        bf16* yp = yout + (size_t)(m0 + wr) * 96;
        yp[lane]      = __float2bfloat16_rn((v0 - mu) * rstd * ga0 + be0);
        yp[lane + 32] = __float2bfloat16_rn((v1 - mu) * rstd * ga1 + be1);
        yp[lane + 64] = __float2bfloat16_rn((v2 - mu) * rstd * ga2 + be2);
    }
}

// ---------------- depthwise 3x3, C=288 bf16, 4-ch chunks, 4-wide x strip ----------------
__global__ void dwconv288_kernel(const bf16* __restrict__ in, const float* __restrict__ kern,
                                 bf16* __restrict__ out) {
    const int C4 = QKV / 4;
    int idx = blockIdx.x * blockDim.x + threadIdx.x;
    if (idx >= (NPIX / 4) * C4) return;
    int c4 = idx % C4;
    int strip = idx / C4;
    int xs = (strip & 63) * 4;
    int y  = (strip >> 6) & 255;
    int b  = strip >> 14;

    float acc[4][4];
    #pragma unroll
    for (int ox = 0; ox < 4; ox++)
        #pragma unroll
        for (int e = 0; e < 4; e++) acc[ox][e] = 0.f;

    #pragma unroll
    for (int dy = -1; dy <= 1; dy++) {
        int yy = y + dy;
        if (yy < 0 || yy > 255) continue;
        const bf16* rowp = in + ((size_t)((b << 8) + yy) << 8) * QKV;
        float v[6][4];
        #pragma unroll
        for (int j = 0; j < 6; j++) {
            int xx = xs - 1 + j;
            if (xx >= 0 && xx <= 255) {
                uint2 u = *(const uint2*)(rowp + (size_t)xx * QKV + c4 * 4);
                float2 f0 = __bfloat1622float2(((const __nv_bfloat162*)&u)[0]);
                float2 f1 = __bfloat1622float2(((const __nv_bfloat162*)&u)[1]);
                v[j][0] = f0.x; v[j][1] = f0.y; v[j][2] = f1.x; v[j][3] = f1.y;
            } else {
                #pragma unroll
                for (int e = 0; e < 4; e++) v[j][e] = 0.f;
            }
        }
        #pragma unroll
        for (int dx = 0; dx < 3; dx++) {
            float4 kv = *(const float4*)(kern + (size_t)((dy + 1) * 3 + dx) * QKV + c4 * 4);
            float kk[4] = {kv.x, kv.y, kv.z, kv.w};
            #pragma unroll
            for (int ox = 0; ox < 4; ox++)
                #pragma unroll
                for (int e = 0; e < 4; e++) acc[ox][e] += v[ox + dx][e] * kk[e];
        }
    }
    bf16* op = out + ((size_t)((b << 16) + (y << 8) + xs)) * QKV + c4 * 4;
    #pragma unroll
    for (int ox = 0; ox < 4; ox++) {
        uint2 u;
        ((uint32_t*)&u)[0] = pack_bf2(acc[ox][0], acc[ox][1]);
        ((uint32_t*)&u)[1] = pack_bf2(acc[ox][2], acc[ox][3]);
        *(uint2*)(op + (size_t)ox * QKV) = u;
    }
}

// ---------------- q*k^T via MMA, warp-pair n-split (36-reg accumulators) ----------------
__global__ void __launch_bounds__(256)
qkt_kernel(const bf16* __restrict__ t1, float* __restrict__ attn, float* __restrict__ nrm) {
    __shared__ __align__(16) bf16 qs[128][56];
    __shared__ __align__(16) bf16 ks[128][56];
    __shared__ float satt[CH][CH];
    __shared__ float nq[48], nk[48];
    int bh = blockIdx.y;
    int b = bh >> 1, hd = bh & 1;
    int s0 = blockIdx.x * 512;
    int tid = threadIdx.x, lane = tid & 31, warp = tid >> 5;
    int pair = warp >> 1, nh = warp & 1;          // pair owns s rows [pair*32, +32); nh picks 24 cols

    for (int i = tid; i < CH * CH; i += 256) ((float*)satt)[i] = 0.f;
    if (tid < 48) { nq[tid] = 0.f; nk[tid] = 0.f; }

    float acc[3][3][4];
    #pragma unroll
    for (int mt = 0; mt < 3; mt++)
        #pragma unroll
        for (int nt = 0; nt < 3; nt++)
            #pragma unroll
            for (int i = 0; i < 4; i++) acc[mt][nt][i] = 0.f;

    const bf16* qbase = t1 + ((size_t)(b << 16)) * QKV + hd * CH;

    int sc4 = tid % 12, sgrp = tid / 12;
    bool stager = (tid < 192);
    float nqa[4] = {0.f, 0.f, 0.f, 0.f}, nka[4] = {0.f, 0.f, 0.f, 0.f};

    uint32_t qs_base = (uint32_t)__cvta_generic_to_shared(&qs[0][0]);
    uint32_t ks_base = (uint32_t)__cvta_generic_to_shared(&ks[0][0]);
    // A (q) trans-ldmatrix x4: k=(lane&7)+((lane>>4)<<3), m=((lane>>3)&1)*8
    int a_k = (lane & 7) + ((lane >> 4) << 3);
    int a_m = ((lane >> 3) & 1) << 3;
    uint32_t a_addr = qs_base + (uint32_t)(((pair * 32 + a_k) * 56 + a_m) * 2);
    // B (k) trans-ldmatrix x2: lanes 0..15 -> k rows 0..15 at col nh*24 (+nt*8)
    uint32_t b_addr = ks_base + (uint32_t)(((pair * 32 + (lane & 15)) * 56 + nh * 24) * 2);

    __syncthreads();

    #pragma unroll 1
    for (int ch = 0; ch < 4; ch++) {
        int sb = s0 + ch * 128;
        if (stager) {
            #pragma unroll
            for (int l = 0; l < 8; l++) {
                int s = sgrp * 8 + l;
                const bf16* qp = qbase + (size_t)(sb + s) * QKV + sc4 * 4;
                uint2 uq = *(const uint2*)qp;
                uint2 uk = *(const uint2*)(qp + CDIM);
                *(uint2*)&qs[s][sc4 * 4] = uq;
                *(uint2*)&ks[s][sc4 * 4] = uk;
                float2 q0 = __bfloat1622float2(((const __nv_bfloat162*)&uq)[0]);
                float2 q1 = __bfloat1622float2(((const __nv_bfloat162*)&uq)[1]);
                float2 k0 = __bfloat1622float2(((const __nv_bfloat162*)&uk)[0]);
                float2 k1 = __bfloat1622float2(((const __nv_bfloat162*)&uk)[1]);
                nqa[0] += q0.x * q0.x; nqa[1] += q0.y * q0.y;
                nqa[2] += q1.x * q1.x; nqa[3] += q1.y * q1.y;
                nka[0] += k0.x * k0.x; nka[1] += k0.y * k0.y;
                nka[2] += k1.x * k1.x; nka[3] += k1.y * k1.y;
            }
        }
        __syncthreads();
        #pragma unroll
        for (int kg = 0; kg < 2; kg++) {
            uint32_t koff = (uint32_t)(kg * 16 * 112);   // 56*2 bytes per row
            uint32_t af[3][4];
            ldsm_x4_t(af[0], a_addr + koff);
            ldsm_x4_t(af[1], a_addr + koff + 32);
            ldsm_x4_t(af[2], a_addr + koff + 64);
            #pragma unroll
            for (int nt = 0; nt < 3; nt++) {
                uint32_t bq[2];
                ldsm_x2_t(bq, b_addr + koff + nt * 16);
                #pragma unroll
                for (int mt = 0; mt < 3; mt++)
                    mma_bf16(acc[mt][nt], af[mt], bq);
            }
        }
        __syncthreads();
    }

    int g = lane >> 2, tg = lane & 3;
    #pragma unroll
    for (int mt = 0; mt < 3; mt++)
        #pragma unroll
        for (int nt = 0; nt < 3; nt++)
            #pragma unroll
            for (int i = 0; i < 4; i++) {
                int row = mt * 16 + g + ((i >> 1) << 3);
                int col = nh * 24 + nt * 8 + tg * 2 + (i & 1);
                atomicAdd(&satt[row][col], acc[mt][nt][i]);
            }
    if (stager) {
        #pragma unroll
        for (int e = 0; e < 4; e++) {
            atomicAdd(&nq[sc4 * 4 + e], nqa[e]);
            atomicAdd(&nk[sc4 * 4 + e], nka[e]);
        }
    }
    __syncthreads();
    float* ab = attn + (size_t)bh * CH * CH;
    for (int i = tid; i < CH * CH; i += 256) atomicAdd(&ab[i], ((float*)satt)[i]);
    if (tid < 48) {
        atomicAdd(&nrm[b * 192 + hd * CH + tid], nq[tid]);
        atomicAdd(&nrm[b * 192 + CDIM + hd * CH + tid], nk[tid]);
    }
}

// ---------------- softmax + fold attention into Wa: M[b, hd*48+e, d] ----------------
__global__ void softmax_fuse_kernel(const float* __restrict__ attn, const float* __restrict__ nrm,
                                    const float* __restrict__ temp, const float* __restrict__ wa,
                                    bf16* __restrict__ M) {
    __shared__ float sa[CH][CH];
    int bh = blockIdx.x;
    int b = bh >> 1, hd = bh & 1;
    int tid = threadIdx.x;
    if (tid < CH) {
        int d = tid;
        float t = temp[hd];
        float rq = rsqrtf(nrm[b * 192 + hd * CH + d]);
        const float* row = attn + (size_t)bh * CH * CH + d * CH;
        float vals[CH];
        float mx = -1e30f;
        #pragma unroll
        for (int e = 0; e < CH; e++) {
            float rk = rsqrtf(nrm[b * 192 + CDIM + hd * CH + e]);
            float v = row[e] * rq * rk * t;
            vals[e] = v;
            mx = fmaxf(mx, v);
        }
        float s = 0.f;
        #pragma unroll
        for (int e = 0; e < CH; e++) { vals[e] = expf(vals[e] - mx); s += vals[e]; }
        float inv = 1.f / s;
        #pragma unroll
        for (int e = 0; e < CH; e++) sa[d][e] = vals[e] * inv;
    }
    __syncthreads();
    for (int i = tid; i < CH * CDIM; i += 256) {
        int e = i / CDIM, d = i % CDIM;
        float s = 0.f;
        #pragma unroll
        for (int cm = 0; cm < CH; cm++)
            s += sa[cm][e] * wa[(size_t)(hd * CH + cm) * CDIM + d];
        M[((size_t)b * CDIM + hd * CH + e) * CDIM + d] = __float2bfloat16_rn(s);
    }
}

// ---------------- depthwise 3x3 + GELU gate: 512-col layout, 2ch x 4px ----------------
__global__ void dwgate_kernel(const bf16* __restrict__ in, const float* __restrict__ kwp,
                              bf16* __restrict__ out) {
    int idx = blockIdx.x * blockDim.x + threadIdx.x;
    int c2 = idx & 127;
    int strip = idx >> 7;
    int xs = (strip & 63) * 4;
    int y  = (strip >> 6) & 255;
    int b  = strip >> 14;

    float accA[4][2], accB[4][2];
    #pragma unroll
    for (int ox = 0; ox < 4; ox++) {
        accA[ox][0] = 0.f; accA[ox][1] = 0.f;
        accB[ox][0] = 0.f; accB[ox][1] = 0.f;
    }

    #pragma unroll
    for (int dy = -1; dy <= 1; dy++) {
        int yy = y + dy;
        if (yy < 0 || yy > 255) continue;
        const bf16* rowp = in + (((size_t)((b << 8) + yy) << 8) << 9);
        float va[6][2], vb[6][2];
        #pragma unroll
        for (int j = 0; j < 6; j++) {
            int xx = xs - 1 + j;
            if (xx >= 0 && xx <= 255) {
                const bf16* pp = rowp + ((size_t)xx << 9) + c2 * 2;
                uint32_t u1 = *(const uint32_t*)pp;
                uint32_t u2 = *(const uint32_t*)(pp + 256);
                float2 f1 = __bfloat1622float2(*(__nv_bfloat162*)&u1);
                float2 f2 = __bfloat1622float2(*(__nv_bfloat162*)&u2);
                va[j][0] = f1.x; va[j][1] = f1.y;
                vb[j][0] = f2.x; vb[j][1] = f2.y;
            } else {
                va[j][0] = 0.f; va[j][1] = 0.f;
                vb[j][0] = 0.f; vb[j][1] = 0.f;
            }
        }
        #pragma unroll
        for (int dx = 0; dx < 3; dx++) {
            int ki = (dy + 1) * 3 + dx;
            float2 k1 = *(const float2*)(kwp + ki * H2P + c2 * 2);
            float2 k2 = *(const float2*)(kwp + ki * H2P + 256 + c2 * 2);
            #pragma unroll
            for (int ox = 0; ox < 4; ox++) {
                accA[ox][0] += va[ox + dx][0] * k1.x;
                accA[ox][1] += va[ox + dx][1] * k1.y;
                accB[ox][0] += vb[ox + dx][0] * k2.x;
                accB[ox][1] += vb[ox + dx][1] * k2.y;
            }
        }
    }
    size_t pbase = (size_t)((b << 16) + (y << 8) + xs);
    #pragma unroll
    for (int ox = 0; ox < 4; ox++) {
        float g0 = gelu_exact(accA[ox][0]) * accB[ox][0];
        float g1 = gelu_exact(accA[ox][1]) * accB[ox][1];
        *(uint32_t*)(out + (pbase + ox) * HIDP + c2 * 2) = pack_bf2(g0, g1);
    }
}

// ---------------- launcher ----------------
extern "C" void kernel_launch(void* const* d_in, const int* in_sizes, int n_in,
                              void* d_out, int out_size) {
    const float* x     = (const float*)d_in[0];
    const float* ln1g  = (const float*)d_in[1];
    const float* ln1b  = (const float*)d_in[2];
    const float* ln2g  = (const float*)d_in[3];
    const float* ln2b  = (const float*)d_in[4];
    const float* qkvw  = (const float*)d_in[5];
    const float* qkvdw = (const float*)d_in[6];
    const float* temp  = (const float*)d_in[7];
    const float* aow   = (const float*)d_in[8];
    const float* fiw   = (const float*)d_in[9];
    const float* fdw   = (const float*)d_in[10];
    const float* fow   = (const float*)d_in[11];
    float* out = (float*)d_out;

    bf16 *t0, *t1, *t2, *gt, *ybf, *wq, *wip, *wo2, *M;
    float *x2, *nrm, *att, *kwp;
    cudaGetSymbolAddress((void**)&t0,  g_t0);
    cudaGetSymbolAddress((void**)&t1,  g_t1);
    cudaGetSymbolAddress((void**)&t2,  g_t2);
    cudaGetSymbolAddress((void**)&gt,  g_gt);
    cudaGetSymbolAddress((void**)&ybf, g_ybf);
    cudaGetSymbolAddress((void**)&x2,  g_x2);
    cudaGetSymbolAddress((void**)&nrm, g_nrm);
    cudaGetSymbolAddress((void**)&att, g_att);
    cudaGetSymbolAddress((void**)&M,   g_M);
    cudaGetSymbolAddress((void**)&wq,  g_wq);
    cudaGetSymbolAddress((void**)&wip, g_wip);
    cudaGetSymbolAddress((void**)&wo2, g_wo2);
    cudaGetSymbolAddress((void**)&kwp, g_kwp);

    const int SMEM_FO = 2 * 128 * 72 * 2 + 256 * 104 * 2;            // 90112
    const int SMEM_QKV = 128 * 104 * 2 + 96 * (288 + 8) * 2;         // 83456
    const int SMEM_FFI = 128 * 104 * 2 + 96 * (256 + 8) * 2;         // 77312
    cudaFuncSetAttribute(gemm_ffnout, cudaFuncAttributeMaxDynamicSharedMemorySize, SMEM_FO);
    cudaFuncSetAttribute((gemm_bres<3, 6, true>),  cudaFuncAttributeMaxDynamicSharedMemorySize, SMEM_QKV);
    cudaFuncSetAttribute((gemm_bres<2, 8, false>), cudaFuncAttributeMaxDynamicSharedMemorySize, SMEM_FFI);

    const int cvt_total = CDIM * QKV + CDIM * H2P;
    cvt_all_kernel<<<(cvt_total + 255) / 256, 256>>>(qkvw, fiw, fow, fdw,
                                                     wq, wip, wo2, kwp, nrm, att);

    // attention branch: fused LN1 + qkv GEMM (B resident)
    gemm_bres<3, 6, true><<<dim3(1, 1024), 256, SMEM_QKV>>>(
        nullptr, x, ln1g, ln1b, wq, t0, QKV);
    dwconv288_kernel<<<(NPIX / 4) * 72 / 256, 256>>>(t0, qkvdw, t1);
    qkt_kernel<<<dim3(128, 4), 256>>>(t1, att, nrm);
    softmax_fuse_kernel<<<4, 256>>>(att, nrm, temp, aow, M);
    // fused: x2 = v@M + x ; ybf = LN2(x2)
    gemm_attnout_ln<<<1024, 256>>>(t1, M, x, x2, ybf, ln2g, ln2b);

    // FFN branch
    gemm_bres<2, 8, false><<<dim3(2, 1024), 256, SMEM_FFI>>>(
        ybf, nullptr, nullptr, nullptr, wip, t2, H2P);
    dwgate_kernel<<<(NPIX / 4) * 128 / 256, 256>>>(t2, kwp, gt);
    gemm_ffnout<<<1024, 256, SMEM_FO>>>(gt, wo2, x2, out);
}